// round 5
// baseline (speedup 1.0000x reference)
#include <cuda_runtime.h>
#include <math.h>

#define NCODES 4096
#define CDIM   256
#define NTOK   32768
#define NC_OUT (NTOK * CDIM)   /* 8388608 */

#define TM 64
#define TN 128
#define KC 64
#define AS_STRIDE 260   /* multiple of 4 (float4 aligned), 4*260 % 32 != 0 */
/* B chunk stored as float2 pairs: pair q holds (code q, code q+64), k-major:
   BsPair[k][q], 64 pairs per k row (512B row). LDS.64 conflict-free.       */
#define SMEM_BYTES ((TM * AS_STRIDE + TN) * 4 + KC * 64 * 8)

typedef unsigned long long u64;

__device__ float g_enorm[NCODES];
__device__ int   g_counts[NCODES];
__device__ float g_loss;
__device__ int   g_valid;
__device__ int   g_idx[NTOK];

/* ------------------------------------------------------------------ */
__global__ void zero_kernel() {
    int i = blockIdx.x * 256 + threadIdx.x;
    if (i < NCODES) g_counts[i] = 0;
    if (i == 0) { g_loss = 0.0f; g_valid = 0; }
}

/* ------------------------------------------------------------------ */
__global__ void enorm_kernel(const float* __restrict__ e) {
    int warp = (blockIdx.x * blockDim.x + threadIdx.x) >> 5;
    int lane = threadIdx.x & 31;
    if (warp >= NCODES) return;
    const float* row = e + (size_t)warp * CDIM;
    float s = 0.0f;
#pragma unroll
    for (int i = 0; i < CDIM / 32; i++) {
        float v = row[lane + 32 * i];
        s += v * v;
    }
#pragma unroll
    for (int o = 16; o; o >>= 1) s += __shfl_down_sync(0xffffffffu, s, o);
    if (lane == 0) g_enorm[warp] = s;
}

/* ------------------------------------------------------------------ */
/* Fused distance-GEMM + argmin, FFMA2 (fma.rn.f32x2) inner loop.      */
/* Each f32x2 FMA = two independent IEEE-rn fp32 FMAs -> bit-identical */
/* to the FFMA version. Distances computed EXACTLY as the reference:   */
/*   d = fl( fl( Z - 2*dot ) + e_norm ),  Z = ||z||^2 (fp32).          */
__global__ __launch_bounds__(256, 2)
void argmin_kernel(const float* __restrict__ z, const float* __restrict__ e,
                   float* __restrict__ out_idx_f) {
    extern __shared__ float sm[];
    float* As     = sm;                        /* [TM][AS_STRIDE] full K   */
    float* BsP    = As + TM * AS_STRIDE;       /* [KC][64] float2 pairs    */
    float* Es     = BsP + KC * 64 * 2;         /* [TN] code norms          */
    const u64* BsP64 = (const u64*)BsP;

    const int tid = threadIdx.x;
    const int tx  = tid & 15;             /* code group  */
    const int ty  = tid >> 4;             /* token group */
    const int t0  = blockIdx.x * TM;

    /* Load A tile (64 tokens x 256 dims), coalesced float4, full K resident */
    {
        const float4* zg = (const float4*)(z + (size_t)t0 * CDIM);
#pragma unroll
        for (int i = 0; i < 16; i++) {
            int v  = tid + i * 256;
            int m  = v >> 6;              /* 64 float4 per token row */
            int k4 = v & 63;
            float4 val = zg[(size_t)m * (CDIM / 4) + k4];
            *(float4*)(As + m * AS_STRIDE + k4 * 4) = val;
        }
    }
    __syncthreads();

    /* Per-token squared norm Z (fp32; summation order is argmin-neutral
       because ulp-multiple shifts preserve the quantized ordering). */
    float Zi[4];
#pragma unroll
    for (int i = 0; i < 4; i++) {
        const float* row = As + (ty + 16 * i) * AS_STRIDE;
        float s = 0.0f;
#pragma unroll 8
        for (int k = 0; k < CDIM; k++) s = fmaf(row[k], row[k], s);
        Zi[i] = s;
    }

    float best[4];
    int   bidx[4];
#pragma unroll
    for (int i = 0; i < 4; i++) { best[i] = 3.4e38f; bidx[i] = 0; }

    for (int jt = 0; jt < NCODES; jt += TN) {
        if (tid < TN) Es[tid] = g_enorm[jt + tid];

        /* acc2[i][j]: low half = code tx+16*j, high half = code tx+16*(j+4) */
        u64 acc2[4][4];
#pragma unroll
        for (int i = 0; i < 4; i++)
#pragma unroll
            for (int j = 0; j < 4; j++) acc2[i][j] = 0ull;

        for (int kc = 0; kc < CDIM; kc += KC) {
            __syncthreads();
            /* Load B chunk: 128 codes x 64 dims -> pair layout BsP[k][q],
               pair q = (code q, code q+64). Coalesced float4 gmem reads. */
#pragma unroll
            for (int i = 0; i < 8; i++) {
                int v  = tid + i * 256;
                int n  = v >> 4;          /* 16 float4 per code-row chunk */
                int k4 = v & 15;
                float4 val = *(const float4*)(e + (size_t)(jt + n) * CDIM + kc + k4 * 4);
                int q    = n & 63;
                int slot = n >> 6;
                float* d0 = BsP + ((4 * k4 + 0) * 64 + q) * 2 + slot;
                d0[0 * 128] = val.x;
                d0[1 * 128] = val.y;
                d0[2 * 128] = val.z;
                d0[3 * 128] = val.w;
            }
            __syncthreads();

#pragma unroll 16
            for (int kk = 0; kk < KC; kk++) {
                u64 a2[4], b2[4];
#pragma unroll
                for (int i = 0; i < 4; i++) {
                    float av = As[(ty + 16 * i) * AS_STRIDE + kc + kk];
                    asm("mov.b64 %0, {%1, %1};"
                        : "=l"(a2[i]) : "r"(__float_as_uint(av)));
                }
#pragma unroll
                for (int j = 0; j < 4; j++)
                    b2[j] = BsP64[kk * 64 + tx + 16 * j];
#pragma unroll
                for (int i = 0; i < 4; i++)
#pragma unroll
                    for (int j = 0; j < 4; j++)
                        asm("fma.rn.f32x2 %0, %1, %2, %0;"
                            : "+l"(acc2[i][j]) : "l"(a2[i]), "l"(b2[j]));
            }
        }

        /* Reference-exact distance: (Z - 2*dot) + e_norm, two roundings */
#pragma unroll
        for (int i = 0; i < 4; i++) {
#pragma unroll
            for (int j = 0; j < 8; j++) {
                u64   p   = acc2[i][j & 3];
                unsigned bits = (j < 4) ? (unsigned)(p & 0xffffffffull)
                                        : (unsigned)(p >> 32);
                float dot = __uint_as_float(bits);
                int   n = jt + tx + 16 * j;
                float t = __fmaf_rn(-2.0f, dot, Zi[i]);
                float d = __fadd_rn(t, Es[tx + 16 * j]);
                if (d < best[i] || (d == best[i] && n < bidx[i])) {
                    best[i] = d; bidx[i] = n;
                }
            }
        }
        __syncthreads();   /* protect Es/BsP before next tile rewrites them */
    }

    /* Cross-thread reduction: 16 lanes (same ty) share 4 tokens each */
#pragma unroll
    for (int i = 0; i < 4; i++) {
        float d = best[i];
        int   n = bidx[i];
#pragma unroll
        for (int o = 8; o; o >>= 1) {
            float od = __shfl_down_sync(0xffffffffu, d, o, 16);
            int   on = __shfl_down_sync(0xffffffffu, n, o, 16);
            if (od < d || (od == d && on < n)) { d = od; n = on; }
        }
        if (tx == 0) {
            int m = ty + 16 * i;
            g_idx[t0 + m]     = n;
            out_idx_f[t0 + m] = (float)n;
        }
    }
}

/* ------------------------------------------------------------------ */
/* Gather z_q / z_q_st, accumulate loss, valid count, code histogram.  */
__global__ void gather_kernel(const float* __restrict__ z,
                              const int* __restrict__ mask,
                              const float* __restrict__ e,
                              float* __restrict__ out) {
    __shared__ float s_loss[8];
    __shared__ int   s_valid[8];
    int wid  = threadIdx.x >> 5;
    int lane = threadIdx.x & 31;
    int t    = blockIdx.x * 8 + wid;

    int mk  = mask[t];
    int idx = g_idx[t];
    const float4* zr = (const float4*)(z + (size_t)t * CDIM);
    const float4* er = (const float4*)(e + (size_t)idx * CDIM);
    float4* o1 = (float4*)(out + (size_t)t * CDIM);
    float4* o2 = (float4*)(out + (size_t)NC_OUT + (size_t)t * CDIM);

    float ls = 0.0f;
#pragma unroll
    for (int i = 0; i < 2; i++) {
        int c = lane + 32 * i;
        float4 ev = er[c];
        float4 zv = zr[c];
        float4 q;
        if (mk) {
            q = ev;
            float dx = ev.x - zv.x, dy = ev.y - zv.y;
            float dz = ev.z - zv.z, dw = ev.w - zv.w;
            ls += dx * dx + dy * dy + dz * dz + dw * dw;
        } else {
            q = make_float4(0.0f, 0.0f, 0.0f, 0.0f);
        }
        o1[c] = q;
        o2[c] = q;
    }
#pragma unroll
    for (int o = 16; o; o >>= 1) ls += __shfl_down_sync(0xffffffffu, ls, o);
    if (lane == 0) {
        s_loss[wid]  = ls;
        s_valid[wid] = mk;
        if (mk) atomicAdd(&g_counts[idx], 1);
    }
    __syncthreads();
    if (threadIdx.x == 0) {
        float tot = 0.0f; int v = 0;
#pragma unroll
        for (int w = 0; w < 8; w++) { tot += s_loss[w]; v += s_valid[w]; }
        atomicAdd(&g_loss, tot);
        atomicAdd(&g_valid, v);
    }
}

/* ------------------------------------------------------------------ */
__global__ void finalize_kernel(float* __restrict__ out) {
    __shared__ float red[256];
    int tid = threadIdx.x;
    float nv    = (float)g_valid;
    float denom = nv + 1e-8f;
    float ent = 0.0f;
    for (int i = tid; i < NCODES; i += 256) {
        float p = (float)g_counts[i] / denom;
        ent += p * logf(p + 1e-8f);
    }
    red[tid] = ent;
    __syncthreads();
    for (int s = 128; s; s >>= 1) {
        if (tid < s) red[tid] += red[tid + s];
        __syncthreads();
    }
    if (tid == 0) {
        float valid = fmaxf(nv, 1.0f);
        float loss  = g_loss / valid;
        float* o = out + 2 * (size_t)NC_OUT + NTOK;
        o[0] = loss * 1.25f;   /* vq_loss = codebook + BETA*commitment */
        o[1] = loss;           /* codebook_loss   */
        o[2] = loss;           /* commitment_loss */
        o[3] = expf(-red[0]);  /* perplexity      */
    }
}

/* ------------------------------------------------------------------ */
extern "C" void kernel_launch(void* const* d_in, const int* in_sizes, int n_in,
                              void* d_out, int out_size) {
    const float* z    = (const float*)d_in[0];
    const int*   mask = (const int*)d_in[1];
    const float* e    = (const float*)d_in[2];
    float*       out  = (float*)d_out;

    cudaFuncSetAttribute(argmin_kernel,
                         cudaFuncAttributeMaxDynamicSharedMemorySize, SMEM_BYTES);

    zero_kernel<<<(NCODES + 255) / 256, 256>>>();
    enorm_kernel<<<NCODES / 8, 256>>>(e);
    argmin_kernel<<<NTOK / TM, 256, SMEM_BYTES>>>(z, e, out + 2 * (size_t)NC_OUT);
    gather_kernel<<<NTOK / 8, 256>>>(z, mask, e, out);
    finalize_kernel<<<1, 256>>>(out);
}

// round 8
// speedup vs baseline: 3.1458x; 3.1458x over previous
#include <cuda_runtime.h>
#include <cuda_bf16.h>
#include <cstdint>
#include <math.h>

#define NCODES 4096
#define CDIM   256
#define NTOK   32768
#define NC_OUT (NTOK * CDIM)

#define TQ      128              /* tokens per CTA           */
#define TNC     128              /* codes per tile           */
#define NTILES  (NCODES / TNC)   /* 32                       */
#define MARGIN  4e-4f
#define CAP     16
#define CAP_OUT 8

/* SMEM layout (bytes) */
#define SM_A      0              /* 64 KB frag-permuted bf16 A  */
#define SM_B      65536          /* 64 KB frag-permuted bf16 B  */
#define SM_ES     131072         /* 128 f32 e_norm              */
#define SM_ROWMIN 131584         /* 128 u32 keyed row minima    */
#define SM_TOT    132096

__device__ float          g_enorm[NCODES];
__device__ int            g_counts[NCODES];
__device__ float          g_loss;
__device__ int            g_valid;
__device__ int            g_idx[NTOK];
__device__ unsigned short g_cand[NTOK * CAP_OUT];
__device__ int            g_ccnt[NTOK];

/* order-preserving float<->uint key for atomicMin */
__device__ __forceinline__ unsigned fkey(float f) {
    unsigned u = __float_as_uint(f);
    return (u & 0x80000000u) ? ~u : (u | 0x80000000u);
}
__device__ __forceinline__ float funkey(unsigned k) {
    return (k & 0x80000000u) ? __uint_as_float(k & 0x7fffffffu)
                             : __uint_as_float(~k);
}

#define MMA_BF16(c, av, bv)                                                     \
    asm volatile("mma.sync.aligned.m16n8k16.row.col.f32.bf16.bf16.f32 "         \
        "{%0,%1,%2,%3}, {%4,%5,%6,%7}, {%8,%9}, {%0,%1,%2,%3};"                 \
        : "+f"((c)[0]), "+f"((c)[1]), "+f"((c)[2]), "+f"((c)[3])                \
        : "r"((av).x), "r"((av).y), "r"((av).z), "r"((av).w),                   \
          "r"((bv).x), "r"((bv).y))

/* ------------------------------------------------------------------ */
__global__ void zero_kernel() {
    int i = blockIdx.x * 256 + threadIdx.x;
    if (i < NCODES) g_counts[i] = 0;
    if (i < NTOK)   g_ccnt[i]   = 0;
    if (i == 0) { g_loss = 0.0f; g_valid = 0; }
}

/* ------------------------------------------------------------------ */
__global__ void enorm_kernel(const float* __restrict__ e) {
    int warp = (blockIdx.x * blockDim.x + threadIdx.x) >> 5;
    int lane = threadIdx.x & 31;
    if (warp >= NCODES) return;
    const float* row = e + (size_t)warp * CDIM;
    float s = 0.0f;
#pragma unroll
    for (int i = 0; i < CDIM / 32; i++) { float v = row[lane + 32 * i]; s += v * v; }
#pragma unroll
    for (int o = 16; o; o >>= 1) s += __shfl_down_sync(0xffffffffu, s, o);
    if (lane == 0) g_enorm[warp] = s;
}

/* ------------------------------------------------------------------ */
/* bf16 mma.sync approx-distance + margin candidate generation.        */
/* et = e_norm - 2*dot_bf16; every possibly-reference-optimal code has */
/* et <= et_min + MARGIN (bf16 dot 6sigma + 2x fp32 rounding @256 <    */
/* 2e-4 < MARGIN).                                                     */
__global__ void __launch_bounds__(256, 1)
cand_kernel(const float* __restrict__ z, const float* __restrict__ e) {
    extern __shared__ char smem[];
    uint32_t* Asm   = (uint32_t*)(smem + SM_A);
    uint32_t* Bsm   = (uint32_t*)(smem + SM_B);
    float*    Es    = (float*)(smem + SM_ES);
    unsigned* rowmin = (unsigned*)(smem + SM_ROWMIN);

    const int tid    = threadIdx.x;
    const int lane   = tid & 31;
    const int wid    = tid >> 5;
    const int warp_m = wid >> 1;    /* 0..3: 32-token stripes */
    const int warp_n = wid & 1;     /* 0..1: 64-code stripes  */
    const int g      = lane >> 2;
    const int tq     = lane & 3;

    if (tid < TQ) rowmin[tid] = 0xFFFFFFFFu;

    /* ---- A: gmem f32 -> bf16 frag-permuted smem (once per CTA) ---- */
    {
        const float* zb = z + (size_t)blockIdx.x * TQ * CDIM;
#pragma unroll 8
        for (int it = 0; it < 64; it++) {
            int v = it * 256 + tid;
            int m = v >> 7, kp = v & 127;
            float2 zv = *(const float2*)(zb + (size_t)m * CDIM + 2 * kp);
            __nv_bfloat162 h = __floats2bfloat162_rn(zv.x, zv.y);
            unsigned u = *(unsigned*)&h;
            int s  = kp >> 3;
            int kk = (2 * kp) & 15;
            int mt = m >> 4, lr = m & 15;
            int lanep = (lr & 7) * 4 + ((kk >> 1) & 3);
            int reg   = (lr >> 3) + 2 * (kk >> 3);
            Asm[(mt * 16 + s) * 128 + ((lanep * 4) ^ ((s & 3) << 2)) + reg] = u;
        }
    }
    __syncthreads();

    float          runmin[4] = {3.4e38f, 3.4e38f, 3.4e38f, 3.4e38f};
    int            cnt[4]    = {0, 0, 0, 0};
    int            ovf       = 0;
    float          ce[4][CAP];
    unsigned short ci[4][CAP];

    auto ins = [&](int sl, float et, int n) {
        if (et <= runmin[sl] + MARGIN) {
            if (et < runmin[sl]) runmin[sl] = et;
            if (cnt[sl] == CAP) {                       /* compact */
                int w = 0; float th = runmin[sl] + MARGIN;
                for (int i = 0; i < CAP; i++)
                    if (ce[sl][i] <= th) { ce[sl][w] = ce[sl][i]; ci[sl][w] = ci[sl][i]; w++; }
                cnt[sl] = w;
            }
            if (cnt[sl] < CAP) { ce[sl][cnt[sl]] = et; ci[sl][cnt[sl]] = (unsigned short)n; cnt[sl]++; }
            else ovf |= 1 << sl;
        }
    };

    for (int tile = 0; tile < NTILES; tile++) {
        const int jt = tile * TNC;
        __syncthreads();            /* previous tile fully consumed */
        if (tid < TNC) Es[tid] = g_enorm[jt + tid];
        {
            const float* eb = e + (size_t)jt * CDIM;
#pragma unroll 8
            for (int it = 0; it < 64; it++) {
                int v = it * 256 + tid;
                int n = v >> 7, kp = v & 127;
                float2 ev = *(const float2*)(eb + (size_t)n * CDIM + 2 * kp);
                __nv_bfloat162 h = __floats2bfloat162_rn(ev.x, ev.y);
                unsigned u = *(unsigned*)&h;
                int s  = kp >> 3;
                int kk = (2 * kp) & 15;
                int nt = n >> 3, nc = n & 7;
                int lanep = nc * 4 + ((kk >> 1) & 3);
                int reg   = kk >> 3;
                Bsm[(nt * 16 + s) * 64 + ((lanep * 2) ^ ((s & 3) << 1)) + reg] = u;
            }
        }
        __syncthreads();

        float acc[2][8][4];
#pragma unroll
        for (int mi = 0; mi < 2; mi++)
#pragma unroll
            for (int nj = 0; nj < 8; nj++)
#pragma unroll
                for (int r = 0; r < 4; r++) acc[mi][nj][r] = 0.0f;

#pragma unroll
        for (int s = 0; s < 16; s++) {
            uint4 a0 = *(const uint4*)(Asm + ((2 * warp_m + 0) * 16 + s) * 128 + ((lane * 4) ^ ((s & 3) << 2)));
            uint4 a1 = *(const uint4*)(Asm + ((2 * warp_m + 1) * 16 + s) * 128 + ((lane * 4) ^ ((s & 3) << 2)));
            uint2 bf[8];
#pragma unroll
            for (int nj = 0; nj < 8; nj++)
                bf[nj] = *(const uint2*)(Bsm + ((8 * warp_n + nj) * 16 + s) * 64 + ((lane * 2) ^ ((s & 3) << 1)));
#pragma unroll
            for (int nj = 0; nj < 8; nj++) {
                MMA_BF16(acc[0][nj], a0, bf[nj]);
                MMA_BF16(acc[1][nj], a1, bf[nj]);
            }
        }

        /* epilogue: C frag -> margin candidates */
#pragma unroll
        for (int mi = 0; mi < 2; mi++)
#pragma unroll
            for (int nj = 0; nj < 8; nj++) {
                int colb = 64 * warp_n + 8 * nj + 2 * tq;
                float e0 = Es[colb], e1 = Es[colb + 1];
                ins(mi * 2 + 0, fmaf(-2.0f, acc[mi][nj][0], e0), jt + colb);
                ins(mi * 2 + 0, fmaf(-2.0f, acc[mi][nj][1], e1), jt + colb + 1);
                ins(mi * 2 + 1, fmaf(-2.0f, acc[mi][nj][2], e0), jt + colb);
                ins(mi * 2 + 1, fmaf(-2.0f, acc[mi][nj][3], e1), jt + colb + 1);
            }
    }

    /* ---- merge: quad-lane min, cross-warp smem atomicMin, refilter ---- */
#pragma unroll
    for (int sl = 0; sl < 4; sl++) {
        float m_ = runmin[sl];
        m_ = fminf(m_, __shfl_xor_sync(0xffffffffu, m_, 1));
        m_ = fminf(m_, __shfl_xor_sync(0xffffffffu, m_, 2));
        int row = 32 * warp_m + 16 * (sl >> 1) + 8 * (sl & 1) + g;
        if (tq == 0) atomicMin(rowmin + row, fkey(m_));
    }
    __syncthreads();
#pragma unroll
    for (int sl = 0; sl < 4; sl++) {
        int row = 32 * warp_m + 16 * (sl >> 1) + 8 * (sl & 1) + g;
        int tok = blockIdx.x * TQ + row;
        float thr = funkey(rowmin[row]) + MARGIN;
        for (int i = 0; i < cnt[sl]; i++)
            if (ce[sl][i] <= thr) {
                int pos = atomicAdd(&g_ccnt[tok], 1);
                if (pos < CAP_OUT) g_cand[tok * CAP_OUT + pos] = ci[sl][i];
            }
        if (ovf & (1 << sl)) atomicAdd(&g_ccnt[tok], 1 << 20);
    }
}

/* ------------------------------------------------------------------ */
/* Exact rescore: reference-exact d = fl(fl(Z-2dot)+e_norm), fp32      */
/* sequential-k (round-4-validated), first-index tie-break.            */
__global__ void rescore_kernel(const float* __restrict__ z, const float* __restrict__ e,
                               float* __restrict__ out_idx_f) {
    int t = blockIdx.x * 256 + threadIdx.x;
    if (t >= NTOK) return;
    int cnt = g_ccnt[t];
    int bi;
    if (cnt == 1) {
        bi = g_cand[t * CAP_OUT];
    } else {
        const float* zr = z + (size_t)t * CDIM;
        float Z = 0.0f;
#pragma unroll 8
        for (int k = 0; k < CDIM; k++) Z = __fmaf_rn(zr[k], zr[k], Z);
        float bd = 3.4e38f; bi = 0;
        if (cnt >= 2 && cnt <= CAP_OUT) {
            for (int c = 0; c < cnt; c++) {
                int idx = g_cand[t * CAP_OUT + c];
                const float* er = e + (size_t)idx * CDIM;
                float dot = 0.0f;
#pragma unroll 8
                for (int k = 0; k < CDIM; k++) dot = __fmaf_rn(zr[k], er[k], dot);
                float d = __fadd_rn(__fmaf_rn(-2.0f, dot, Z), g_enorm[idx]);
                if (d < bd || (d == bd && idx < bi)) { bd = d; bi = idx; }
            }
        } else {      /* overflow fallback: exact scan of all codes */
            for (int idx = 0; idx < NCODES; idx++) {
                const float* er = e + (size_t)idx * CDIM;
                float dot = 0.0f;
#pragma unroll 8
                for (int k = 0; k < CDIM; k++) dot = __fmaf_rn(zr[k], er[k], dot);
                float d = __fadd_rn(__fmaf_rn(-2.0f, dot, Z), g_enorm[idx]);
                if (d < bd) { bd = d; bi = idx; }
            }
        }
    }
    g_idx[t] = bi;
    out_idx_f[t] = (float)bi;
}

/* ------------------------------------------------------------------ */
__global__ void gather_kernel(const float* __restrict__ z,
                              const int* __restrict__ mask,
                              const float* __restrict__ e,
                              float* __restrict__ out) {
    __shared__ float s_loss[8];
    __shared__ int   s_valid[8];
    int wid  = threadIdx.x >> 5;
    int lane = threadIdx.x & 31;
    int t    = blockIdx.x * 8 + wid;

    int mk  = mask[t];
    int idx = g_idx[t];
    const float4* zr = (const float4*)(z + (size_t)t * CDIM);
    const float4* er = (const float4*)(e + (size_t)idx * CDIM);
    float4* o1 = (float4*)(out + (size_t)t * CDIM);
    float4* o2 = (float4*)(out + (size_t)NC_OUT + (size_t)t * CDIM);

    float ls = 0.0f;
#pragma unroll
    for (int i = 0; i < 2; i++) {
        int c = lane + 32 * i;
        float4 ev = er[c];
        float4 zv = zr[c];
        float4 q;
        if (mk) {
            q = ev;
            float dx = ev.x - zv.x, dy = ev.y - zv.y;
            float dz = ev.z - zv.z, dw = ev.w - zv.w;
            ls += dx * dx + dy * dy + dz * dz + dw * dw;
        } else {
            q = make_float4(0.0f, 0.0f, 0.0f, 0.0f);
        }
        o1[c] = q;
        o2[c] = q;
    }
#pragma unroll
    for (int o = 16; o; o >>= 1) ls += __shfl_down_sync(0xffffffffu, ls, o);
    if (lane == 0) {
        s_loss[wid]  = ls;
        s_valid[wid] = mk;
        if (mk) atomicAdd(&g_counts[idx], 1);
    }
    __syncthreads();
    if (threadIdx.x == 0) {
        float tot = 0.0f; int v = 0;
#pragma unroll
        for (int w = 0; w < 8; w++) { tot += s_loss[w]; v += s_valid[w]; }
        atomicAdd(&g_loss, tot);
        atomicAdd(&g_valid, v);
    }
}

/* ------------------------------------------------------------------ */
__global__ void finalize_kernel(float* __restrict__ out) {
    __shared__ float red[256];
    int tid = threadIdx.x;
    float nv    = (float)g_valid;
    float denom = nv + 1e-8f;
    float ent = 0.0f;
    for (int i = tid; i < NCODES; i += 256) {
        float p = (float)g_counts[i] / denom;
        ent += p * logf(p + 1e-8f);
    }
    red[tid] = ent;
    __syncthreads();
    for (int s = 128; s; s >>= 1) {
        if (tid < s) red[tid] += red[tid + s];
        __syncthreads();
    }
    if (tid == 0) {
        float valid = fmaxf(nv, 1.0f);
        float loss  = g_loss / valid;
        float* o = out + 2 * (size_t)NC_OUT + NTOK;
        o[0] = loss * 1.25f;   /* vq_loss = codebook + BETA*commitment */
        o[1] = loss;           /* codebook_loss   */
        o[2] = loss;           /* commitment_loss */
        o[3] = expf(-red[0]);  /* perplexity      */
    }
}

/* ------------------------------------------------------------------ */
extern "C" void kernel_launch(void* const* d_in, const int* in_sizes, int n_in,
                              void* d_out, int out_size) {
    const float* z    = (const float*)d_in[0];
    const int*   mask = (const int*)d_in[1];
    const float* e    = (const float*)d_in[2];
    float*       out  = (float*)d_out;

    cudaFuncSetAttribute(cand_kernel,
                         cudaFuncAttributeMaxDynamicSharedMemorySize, SM_TOT);

    zero_kernel<<<NTOK / 256, 256>>>();
    enorm_kernel<<<NCODES / 8, 256>>>(e);
    cand_kernel<<<NTOK / TQ, 256, SM_TOT>>>(z, e);
    rescore_kernel<<<NTOK / 256, 256>>>(z, e, out + 2 * (size_t)NC_OUT);
    gather_kernel<<<NTOK / 8, 256>>>(z, mask, e, out);
    finalize_kernel<<<1, 256>>>(out);
}

// round 9
// speedup vs baseline: 3.4415x; 1.0940x over previous
#include <cuda_runtime.h>
#include <cuda_bf16.h>
#include <cstdint>
#include <math.h>

#define NCODES 4096
#define CDIM   256
#define NTOK   32768
#define NC_OUT (NTOK * CDIM)

#define TQ      128              /* tokens per CTA           */
#define TNC     128              /* codes per tile           */
#define NTILES  (NCODES / TNC)   /* 32                       */
#define MARGIN  4e-4f
#define CAP     16
#define CAP_OUT 8

#define TILE_U32 16384           /* 64 KB per permuted tile  */

/* SMEM layout (bytes): A 64K | B0 64K | B1 64K | Es | rowmin */
#define SM_A      0
#define SM_B0     65536
#define SM_B1     131072
#define SM_ES     196608
#define SM_ROWMIN 197120
#define SM_TOT    197632

__device__ float          g_enorm[NCODES];
__device__ int            g_counts[NCODES];
__device__ float          g_loss;
__device__ int            g_valid;
__device__ int            g_idx[NTOK];
__device__ unsigned short g_cand[NTOK * CAP_OUT];
__device__ int            g_ccnt[NTOK];
__device__ unsigned long long g_key[NTOK];
__device__ uint32_t       g_eperm[NTILES * TILE_U32];        /* 2 MB  */
__device__ uint32_t       g_zperm[(NTOK / TQ) * TILE_U32];   /* 16 MB */

/* order-preserving float<->uint key */
__device__ __forceinline__ unsigned fkey(float f) {
    unsigned u = __float_as_uint(f);
    return (u & 0x80000000u) ? ~u : (u | 0x80000000u);
}
__device__ __forceinline__ float funkey(unsigned k) {
    return (k & 0x80000000u) ? __uint_as_float(k & 0x7fffffffu)
                             : __uint_as_float(~k);
}
__device__ __forceinline__ uint32_t smem_u32(const void* p) {
    uint32_t a;
    asm("{ .reg .u64 t; cvta.to.shared.u64 t, %1; cvt.u32.u64 %0, t; }" : "=r"(a) : "l"(p));
    return a;
}
#define CP_ASYNC16(dst, src) \
    asm volatile("cp.async.cg.shared.global [%0], [%1], 16;" :: "r"(dst), "l"(src) : "memory")
#define CP_COMMIT()  asm volatile("cp.async.commit_group;" ::: "memory")
#define CP_WAIT(n)   asm volatile("cp.async.wait_group %0;" :: "n"(n) : "memory")

#define MMA_BF16(c, av, bv)                                                     \
    asm volatile("mma.sync.aligned.m16n8k16.row.col.f32.bf16.bf16.f32 "         \
        "{%0,%1,%2,%3}, {%4,%5,%6,%7}, {%8,%9}, {%0,%1,%2,%3};"                 \
        : "+f"((c)[0]), "+f"((c)[1]), "+f"((c)[2]), "+f"((c)[3])                \
        : "r"((av).x), "r"((av).y), "r"((av).z), "r"((av).w),                   \
          "r"((bv).x), "r"((bv).y))

/* ------------------------------------------------------------------ */
__global__ void zero_kernel() {
    int i = blockIdx.x * 256 + threadIdx.x;
    if (i < NCODES) g_counts[i] = 0;
    if (i < NTOK) { g_ccnt[i] = 0; g_key[i] = 0xFFFFFFFFFFFFFFFFull; }
    if (i == 0) { g_loss = 0.0f; g_valid = 0; }
}

/* ------------------------------------------------------------------ */
__global__ void enorm_kernel(const float* __restrict__ e) {
    int warp = (blockIdx.x * blockDim.x + threadIdx.x) >> 5;
    int lane = threadIdx.x & 31;
    if (warp >= NCODES) return;
    const float* row = e + (size_t)warp * CDIM;
    float s = 0.0f;
#pragma unroll
    for (int i = 0; i < CDIM / 32; i++) { float v = row[lane + 32 * i]; s += v * v; }
#pragma unroll
    for (int o = 16; o; o >>= 1) s += __shfl_down_sync(0xffffffffu, s, o);
    if (lane == 0) g_enorm[warp] = s;
}

/* ------------------------------------------------------------------ */
/* Pre-permute codebook/tokens to bf16 in the exact fragment layout    */
/* the MMA loop consumes (identical cvt -> identical MMA inputs).      */
__global__ void eperm_kernel(const float* __restrict__ e) {
    int v  = blockIdx.x * 256 + threadIdx.x;        /* NCODES*128 pairs */
    int ng = v >> 7, kp = v & 127;
    float2 ev = *(const float2*)(e + (size_t)ng * CDIM + 2 * kp);
    __nv_bfloat162 h = __floats2bfloat162_rn(ev.x, ev.y);
    int tile = ng >> 7, n = ng & 127;
    int s = kp >> 3, kk = (2 * kp) & 15;
    int nt = n >> 3, nc = n & 7;
    int lanep = nc * 4 + ((kk >> 1) & 3);
    int reg   = kk >> 3;
    g_eperm[tile * TILE_U32 + (nt * 16 + s) * 64 + ((lanep * 2) ^ ((s & 3) << 1)) + reg]
        = *(unsigned*)&h;
}

__global__ void zperm_kernel(const float* __restrict__ z) {
    int v  = blockIdx.x * 256 + threadIdx.x;        /* NTOK*128 pairs */
    int mg = v >> 7, kp = v & 127;
    float2 zv = *(const float2*)(z + (size_t)mg * CDIM + 2 * kp);
    __nv_bfloat162 h = __floats2bfloat162_rn(zv.x, zv.y);
    int blk = mg >> 7, m = mg & 127;
    int s = kp >> 3, kk = (2 * kp) & 15;
    int mt = m >> 4, lr = m & 15;
    int lanep = (lr & 7) * 4 + ((kk >> 1) & 3);
    int reg   = (lr >> 3) + 2 * (kk >> 3);
    g_zperm[blk * TILE_U32 + (mt * 16 + s) * 128 + ((lanep * 4) ^ ((s & 3) << 2)) + reg]
        = *(unsigned*)&h;
}

/* ------------------------------------------------------------------ */
/* bf16 mma.sync approx-distance + margin candidates. Pipeline:        */
/* cp.async double-buffered pre-permuted B tiles overlap MMA.          */
__global__ void __launch_bounds__(256, 1)
cand_kernel() {
    extern __shared__ char smem[];
    uint32_t* Asm    = (uint32_t*)(smem + SM_A);
    float*    Es     = (float*)(smem + SM_ES);
    unsigned* rowmin = (unsigned*)(smem + SM_ROWMIN);
    const uint32_t sbase = smem_u32(smem);

    const int tid    = threadIdx.x;
    const int lane   = tid & 31;
    const int wid    = tid >> 5;
    const int warp_m = wid >> 1;
    const int warp_n = wid & 1;
    const int g      = lane >> 2;
    const int tq     = lane & 3;

    if (tid < TQ) rowmin[tid] = 0xFFFFFFFFu;

    /* prologue: A + B tile 0 via cp.async (group 0) */
    {
        const uint32_t* Ag = g_zperm + (size_t)blockIdx.x * TILE_U32;
        const uint32_t* Bg = g_eperm;
#pragma unroll
        for (int i = 0; i < 16; i++) {
            int o = (i * 256 + tid) * 4;
            CP_ASYNC16(sbase + SM_A  + o * 4, Ag + o);
            CP_ASYNC16(sbase + SM_B0 + o * 4, Bg + o);
        }
        CP_COMMIT();
    }

    float          runmin[4] = {3.4e38f, 3.4e38f, 3.4e38f, 3.4e38f};
    int            cnt[4]    = {0, 0, 0, 0};
    int            ovf       = 0;
    float          ce[4][CAP];
    unsigned short ci[4][CAP];

    auto ins = [&](int sl, float et, int n) {
        if (et <= runmin[sl] + MARGIN) {
            if (et < runmin[sl]) runmin[sl] = et;
            if (cnt[sl] == CAP) {
                int w = 0; float th = runmin[sl] + MARGIN;
                for (int i = 0; i < CAP; i++)
                    if (ce[sl][i] <= th) { ce[sl][w] = ce[sl][i]; ci[sl][w] = ci[sl][i]; w++; }
                cnt[sl] = w;
            }
            if (cnt[sl] < CAP) { ce[sl][cnt[sl]] = et; ci[sl][cnt[sl]] = (unsigned short)n; cnt[sl]++; }
            else ovf |= 1 << sl;
        }
    };

    int buf = 0;
    for (int tile = 0; tile < NTILES; tile++) {
        const int jt = tile * TNC;
        if (tile + 1 < NTILES) {        /* prefetch next B into other buffer */
            const uint32_t* Bg = g_eperm + (size_t)(tile + 1) * TILE_U32;
            uint32_t dstb = sbase + (buf ? SM_B0 : SM_B1);
#pragma unroll
            for (int i = 0; i < 16; i++) {
                int o = (i * 256 + tid) * 4;
                CP_ASYNC16(dstb + o * 4, Bg + o);
            }
            CP_COMMIT();
            CP_WAIT(1);
        } else {
            CP_WAIT(0);
        }
        if (tid < TNC) Es[tid] = g_enorm[jt + tid];
        __syncthreads();

        const uint32_t* Bsm = (const uint32_t*)(smem + (buf ? SM_B1 : SM_B0));

        float acc[2][8][4];
#pragma unroll
        for (int mi = 0; mi < 2; mi++)
#pragma unroll
            for (int nj = 0; nj < 8; nj++)
#pragma unroll
                for (int r = 0; r < 4; r++) acc[mi][nj][r] = 0.0f;

#pragma unroll
        for (int s = 0; s < 16; s++) {
            uint4 a0 = *(const uint4*)(Asm + ((2 * warp_m + 0) * 16 + s) * 128 + ((lane * 4) ^ ((s & 3) << 2)));
            uint4 a1 = *(const uint4*)(Asm + ((2 * warp_m + 1) * 16 + s) * 128 + ((lane * 4) ^ ((s & 3) << 2)));
            uint2 bf[8];
#pragma unroll
            for (int nj = 0; nj < 8; nj++)
                bf[nj] = *(const uint2*)(Bsm + ((8 * warp_n + nj) * 16 + s) * 64 + ((lane * 2) ^ ((s & 3) << 1)));
#pragma unroll
            for (int nj = 0; nj < 8; nj++) {
                MMA_BF16(acc[0][nj], a0, bf[nj]);
                MMA_BF16(acc[1][nj], a1, bf[nj]);
            }
        }

#pragma unroll
        for (int mi = 0; mi < 2; mi++)
#pragma unroll
            for (int nj = 0; nj < 8; nj++) {
                int colb = 64 * warp_n + 8 * nj + 2 * tq;
                float e0 = Es[colb], e1 = Es[colb + 1];
                ins(mi * 2 + 0, fmaf(-2.0f, acc[mi][nj][0], e0), jt + colb);
                ins(mi * 2 + 0, fmaf(-2.0f, acc[mi][nj][1], e1), jt + colb + 1);
                ins(mi * 2 + 1, fmaf(-2.0f, acc[mi][nj][2], e0), jt + colb);
                ins(mi * 2 + 1, fmaf(-2.0f, acc[mi][nj][3], e1), jt + colb + 1);
            }
        __syncthreads();               /* epilogue done before buf reuse */
        buf ^= 1;
    }

    /* merge: quad-lane min, cross-warp smem atomicMin, refilter */
#pragma unroll
    for (int sl = 0; sl < 4; sl++) {
        float m_ = runmin[sl];
        m_ = fminf(m_, __shfl_xor_sync(0xffffffffu, m_, 1));
        m_ = fminf(m_, __shfl_xor_sync(0xffffffffu, m_, 2));
        int row = 32 * warp_m + 16 * (sl >> 1) + 8 * (sl & 1) + g;
        if (tq == 0) atomicMin(rowmin + row, fkey(m_));
    }
    __syncthreads();
#pragma unroll
    for (int sl = 0; sl < 4; sl++) {
        int row = 32 * warp_m + 16 * (sl >> 1) + 8 * (sl & 1) + g;
        int tok = blockIdx.x * TQ + row;
        float thr = funkey(rowmin[row]) + MARGIN;
        for (int i = 0; i < cnt[sl]; i++)
            if (ce[sl][i] <= thr) {
                int pos = atomicAdd(&g_ccnt[tok], 1);
                if (pos < CAP_OUT) g_cand[tok * CAP_OUT + pos] = ci[sl][i];
            }
        if (ovf & (1 << sl)) atomicAdd(&g_ccnt[tok], 1 << 20);
    }
}

/* ------------------------------------------------------------------ */
/* Rescore phase A: one thread per (token, candidate); per-candidate   */
/* arithmetic byte-identical to the validated sequential-k version.    */
/* Winner via atomicMin on (fkey(d)<<32)|idx  == same min/tie rule.    */
__global__ void rescoreA_kernel(const float* __restrict__ z, const float* __restrict__ e) {
    int gid = blockIdx.x * 256 + threadIdx.x;
    int t = gid >> 3, c = gid & 7;
    int cnt = g_ccnt[t];
    if (cnt < 2 || cnt > CAP_OUT || c >= cnt) return;

    const float* zr = z + (size_t)t * CDIM;
    float Z = 0.0f;
#pragma unroll 8
    for (int k = 0; k < CDIM; k++) Z = __fmaf_rn(zr[k], zr[k], Z);

    int idx = g_cand[t * CAP_OUT + c];
    const float* er = e + (size_t)idx * CDIM;
    float dot = 0.0f;
#pragma unroll 8
    for (int k = 0; k < CDIM; k++) dot = __fmaf_rn(zr[k], er[k], dot);
    float d = __fadd_rn(__fmaf_rn(-2.0f, dot, Z), g_enorm[idx]);

    unsigned long long key = ((unsigned long long)fkey(d) << 32) | (unsigned)idx;
    atomicMin(&g_key[t], key);
}

/* Rescore phase B: pick winner / fast path / rare full-scan fallback. */
__global__ void rescoreB_kernel(const float* __restrict__ z, const float* __restrict__ e,
                                float* __restrict__ out_idx_f) {
    int t = blockIdx.x * 256 + threadIdx.x;
    if (t >= NTOK) return;
    int cnt = g_ccnt[t];
    int bi;
    if (cnt == 1) {
        bi = g_cand[t * CAP_OUT];
    } else if (cnt >= 2 && cnt <= CAP_OUT) {
        bi = (int)(unsigned)(g_key[t] & 0xFFFFFFFFull);
    } else {        /* overflow fallback: exact scan of all codes */
        const float* zr = z + (size_t)t * CDIM;
        float Z = 0.0f;
#pragma unroll 8
        for (int k = 0; k < CDIM; k++) Z = __fmaf_rn(zr[k], zr[k], Z);
        float bd = 3.4e38f; bi = 0;
        for (int idx = 0; idx < NCODES; idx++) {
            const float* er = e + (size_t)idx * CDIM;
            float dot = 0.0f;
#pragma unroll 8
            for (int k = 0; k < CDIM; k++) dot = __fmaf_rn(zr[k], er[k], dot);
            float d = __fadd_rn(__fmaf_rn(-2.0f, dot, Z), g_enorm[idx]);
            if (d < bd) { bd = d; bi = idx; }
        }
    }
    g_idx[t] = bi;
    out_idx_f[t] = (float)bi;
}

/* ------------------------------------------------------------------ */
__global__ void gather_kernel(const float* __restrict__ z,
                              const int* __restrict__ mask,
                              const float* __restrict__ e,
                              float* __restrict__ out) {
    __shared__ float s_loss[8];
    __shared__ int   s_valid[8];
    int wid  = threadIdx.x >> 5;
    int lane = threadIdx.x & 31;
    int t    = blockIdx.x * 8 + wid;

    int mk  = mask[t];
    int idx = g_idx[t];
    const float4* zr = (const float4*)(z + (size_t)t * CDIM);
    const float4* er = (const float4*)(e + (size_t)idx * CDIM);
    float4* o1 = (float4*)(out + (size_t)t * CDIM);
    float4* o2 = (float4*)(out + (size_t)NC_OUT + (size_t)t * CDIM);

    float ls = 0.0f;
#pragma unroll
    for (int i = 0; i < 2; i++) {
        int c = lane + 32 * i;
        float4 ev = er[c];
        float4 zv = zr[c];
        float4 q;
        if (mk) {
            q = ev;
            float dx = ev.x - zv.x, dy = ev.y - zv.y;
            float dz = ev.z - zv.z, dw = ev.w - zv.w;
            ls += dx * dx + dy * dy + dz * dz + dw * dw;
        } else {
            q = make_float4(0.0f, 0.0f, 0.0f, 0.0f);
        }
        o1[c] = q;
        o2[c] = q;
    }
#pragma unroll
    for (int o = 16; o; o >>= 1) ls += __shfl_down_sync(0xffffffffu, ls, o);
    if (lane == 0) {
        s_loss[wid]  = ls;
        s_valid[wid] = mk;
        if (mk) atomicAdd(&g_counts[idx], 1);
    }
    __syncthreads();
    if (threadIdx.x == 0) {
        float tot = 0.0f; int v = 0;
#pragma unroll
        for (int w = 0; w < 8; w++) { tot += s_loss[w]; v += s_valid[w]; }
        atomicAdd(&g_loss, tot);
        atomicAdd(&g_valid, v);
    }
}

/* ------------------------------------------------------------------ */
__global__ void finalize_kernel(float* __restrict__ out) {
    __shared__ float red[256];
    int tid = threadIdx.x;
    float nv    = (float)g_valid;
    float denom = nv + 1e-8f;
    float ent = 0.0f;
    for (int i = tid; i < NCODES; i += 256) {
        float p = (float)g_counts[i] / denom;
        ent += p * logf(p + 1e-8f);
    }
    red[tid] = ent;
    __syncthreads();
    for (int s = 128; s; s >>= 1) {
        if (tid < s) red[tid] += red[tid + s];
        __syncthreads();
    }
    if (tid == 0) {
        float valid = fmaxf(nv, 1.0f);
        float loss  = g_loss / valid;
        float* o = out + 2 * (size_t)NC_OUT + NTOK;
        o[0] = loss * 1.25f;
        o[1] = loss;
        o[2] = loss;
        o[3] = expf(-red[0]);
    }
}

/* ------------------------------------------------------------------ */
extern "C" void kernel_launch(void* const* d_in, const int* in_sizes, int n_in,
                              void* d_out, int out_size) {
    const float* z    = (const float*)d_in[0];
    const int*   mask = (const int*)d_in[1];
    const float* e    = (const float*)d_in[2];
    float*       out  = (float*)d_out;

    cudaFuncSetAttribute(cand_kernel,
                         cudaFuncAttributeMaxDynamicSharedMemorySize, SM_TOT);

    zero_kernel<<<NTOK / 256, 256>>>();
    enorm_kernel<<<NCODES / 8, 256>>>(e);
    eperm_kernel<<<NCODES * 128 / 256, 256>>>(e);
    zperm_kernel<<<NTOK * 128 / 256, 256>>>(z);
    cand_kernel<<<NTOK / TQ, 256, SM_TOT>>>();
    rescoreA_kernel<<<NTOK * CAP_OUT / 256, 256>>>(z, e);
    rescoreB_kernel<<<NTOK / 256, 256>>>(z, e, out + 2 * (size_t)NC_OUT);
    gather_kernel<<<NTOK / 8, 256>>>(z, mask, e, out);
    finalize_kernel<<<1, 256>>>(out);
}

// round 10
// speedup vs baseline: 4.6006x; 1.3368x over previous
#include <cuda_runtime.h>
#include <cuda_bf16.h>
#include <cstdint>
#include <math.h>

#define NCODES 4096
#define CDIM   256
#define NTOK   32768
#define NC_OUT (NTOK * CDIM)

#define TQ      128              /* tokens per CTA           */
#define TNC     128              /* codes per tile           */
#define NTILES  (NCODES / TNC)   /* 32                       */
#define MARGIN  4e-4f
#define CAP_OUT 8

#define TILE_U32 16384           /* 64 KB per permuted tile  */

/* SMEM layout (bytes): A 64K | B0 64K | B1 64K | Es | rowmin */
#define SM_A      0
#define SM_B0     65536
#define SM_B1     131072
#define SM_ES     196608
#define SM_ROWMIN 197120
#define SM_TOT    197632

__device__ float          g_enorm[NCODES];
__device__ int            g_counts[NCODES];
__device__ float          g_loss;
__device__ int            g_valid;
__device__ int            g_idx[NTOK];
__device__ unsigned short g_cand[NTOK * CAP_OUT];
__device__ int            g_ccnt[NTOK];
__device__ unsigned long long g_key[NTOK];
__device__ uint32_t       g_eperm[NTILES * TILE_U32];        /* 2 MB  */
__device__ uint32_t       g_zperm[(NTOK / TQ) * TILE_U32];   /* 16 MB */

/* order-preserving float<->uint key */
__device__ __forceinline__ unsigned fkey(float f) {
    unsigned u = __float_as_uint(f);
    return (u & 0x80000000u) ? ~u : (u | 0x80000000u);
}
__device__ __forceinline__ float funkey(unsigned k) {
    return (k & 0x80000000u) ? __uint_as_float(k & 0x7fffffffu)
                             : __uint_as_float(~k);
}
__device__ __forceinline__ uint32_t smem_u32(const void* p) {
    uint32_t a;
    asm("{ .reg .u64 t; cvta.to.shared.u64 t, %1; cvt.u32.u64 %0, t; }" : "=r"(a) : "l"(p));
    return a;
}
#define CP_ASYNC16(dst, src) \
    asm volatile("cp.async.cg.shared.global [%0], [%1], 16;" :: "r"(dst), "l"(src) : "memory")
#define CP_COMMIT()  asm volatile("cp.async.commit_group;" ::: "memory")
#define CP_WAIT(n)   asm volatile("cp.async.wait_group %0;" :: "n"(n) : "memory")

#define MMA_BF16(c, av, bv)                                                     \
    asm volatile("mma.sync.aligned.m16n8k16.row.col.f32.bf16.bf16.f32 "         \
        "{%0,%1,%2,%3}, {%4,%5,%6,%7}, {%8,%9}, {%0,%1,%2,%3};"                 \
        : "+f"((c)[0]), "+f"((c)[1]), "+f"((c)[2]), "+f"((c)[3])                \
        : "r"((av).x), "r"((av).y), "r"((av).z), "r"((av).w),                   \
          "r"((bv).x), "r"((bv).y))

/* ------------------------------------------------------------------ */
__global__ void zero_kernel() {
    int i = blockIdx.x * 256 + threadIdx.x;
    if (i < NCODES) g_counts[i] = 0;
    if (i < NTOK) { g_ccnt[i] = 0; g_key[i] = 0xFFFFFFFFFFFFFFFFull; }
    if (i == 0) { g_loss = 0.0f; g_valid = 0; }
}

/* ------------------------------------------------------------------ */
__global__ void enorm_kernel(const float* __restrict__ e) {
    int warp = (blockIdx.x * blockDim.x + threadIdx.x) >> 5;
    int lane = threadIdx.x & 31;
    if (warp >= NCODES) return;
    const float* row = e + (size_t)warp * CDIM;
    float s = 0.0f;
#pragma unroll
    for (int i = 0; i < CDIM / 32; i++) { float v = row[lane + 32 * i]; s += v * v; }
#pragma unroll
    for (int o = 16; o; o >>= 1) s += __shfl_down_sync(0xffffffffu, s, o);
    if (lane == 0) g_enorm[warp] = s;
}

/* ------------------------------------------------------------------ */
/* Pre-permute codebook/tokens to bf16 fragment layout.                */
__global__ void eperm_kernel(const float* __restrict__ e) {
    int v  = blockIdx.x * 256 + threadIdx.x;        /* NCODES*128 pairs */
    int ng = v >> 7, kp = v & 127;
    float2 ev = *(const float2*)(e + (size_t)ng * CDIM + 2 * kp);
    __nv_bfloat162 h = __floats2bfloat162_rn(ev.x, ev.y);
    int tile = ng >> 7, n = ng & 127;
    int s = kp >> 3, kk = (2 * kp) & 15;
    int nt = n >> 3, nc = n & 7;
    int lanep = nc * 4 + ((kk >> 1) & 3);
    int reg   = kk >> 3;
    g_eperm[tile * TILE_U32 + (nt * 16 + s) * 64 + ((lanep * 2) ^ ((s & 3) << 1)) + reg]
        = *(unsigned*)&h;
}

__global__ void zperm_kernel(const float* __restrict__ z) {
    int v  = blockIdx.x * 256 + threadIdx.x;        /* NTOK*128 pairs */
    int mg = v >> 7, kp = v & 127;
    float2 zv = *(const float2*)(z + (size_t)mg * CDIM + 2 * kp);
    __nv_bfloat162 h = __floats2bfloat162_rn(zv.x, zv.y);
    int blk = mg >> 7, m = mg & 127;
    int s = kp >> 3, kk = (2 * kp) & 15;
    int mt = m >> 4, lr = m & 15;
    int lanep = (lr & 7) * 4 + ((kk >> 1) & 3);
    int reg   = (lr >> 3) + 2 * (kk >> 3);
    g_zperm[blk * TILE_U32 + (mt * 16 + s) * 128 + ((lanep * 4) ^ ((s & 3) << 2)) + reg]
        = *(unsigned*)&h;
}

/* ------------------------------------------------------------------ */
/* Two-phase bf16 mma.sync candidate generation (zero local-memory):   */
/*  pass 0: branch-free running min of et = e_norm - 2*dot_bf16        */
/*  merge : quad shuffle + smem atomicMin(fkey) -> exact token min     */
/*  pass 1: identical deterministic MMA; append et <= min + MARGIN     */
/* Candidate-set semantics identical to rounds 8-9 (margin proof).     */
__global__ void __launch_bounds__(256, 1)
cand_kernel() {
    extern __shared__ char smem[];
    uint32_t* Asm    = (uint32_t*)(smem + SM_A);
    float*    Es     = (float*)(smem + SM_ES);
    unsigned* rowmin = (unsigned*)(smem + SM_ROWMIN);
    const uint32_t sbase = smem_u32(smem);

    const int tid    = threadIdx.x;
    const int lane   = tid & 31;
    const int wid    = tid >> 5;
    const int warp_m = wid >> 1;
    const int warp_n = wid & 1;
    const int g      = lane >> 2;
    const int tq     = lane & 3;

    if (tid < TQ) rowmin[tid] = 0xFFFFFFFFu;

    /* A tile via cp.async (resident across both passes) */
    {
        const uint32_t* Ag = g_zperm + (size_t)blockIdx.x * TILE_U32;
#pragma unroll
        for (int i = 0; i < 16; i++) {
            int o = (i * 256 + tid) * 4;
            CP_ASYNC16(sbase + SM_A + o * 4, Ag + o);
        }
        CP_COMMIT();
    }

    float runmin[4] = {3.4e38f, 3.4e38f, 3.4e38f, 3.4e38f};
    float thrv[4];

#pragma unroll 1
    for (int pass = 0; pass < 2; pass++) {
        /* prologue: B tile 0 into buffer 0 */
        {
            const uint32_t* Bg = g_eperm;
#pragma unroll
            for (int i = 0; i < 16; i++) {
                int o = (i * 256 + tid) * 4;
                CP_ASYNC16(sbase + SM_B0 + o * 4, Bg + o);
            }
            CP_COMMIT();
        }

        int buf = 0;
#pragma unroll 1
        for (int tile = 0; tile < NTILES; tile++) {
            const int jt = tile * TNC;
            if (tile + 1 < NTILES) {
                const uint32_t* Bg = g_eperm + (size_t)(tile + 1) * TILE_U32;
                uint32_t dstb = sbase + (buf ? SM_B0 : SM_B1);
#pragma unroll
                for (int i = 0; i < 16; i++) {
                    int o = (i * 256 + tid) * 4;
                    CP_ASYNC16(dstb + o * 4, Bg + o);
                }
                CP_COMMIT();
                CP_WAIT(1);
            } else {
                CP_WAIT(0);
            }
            if (tid < TNC) Es[tid] = g_enorm[jt + tid];
            __syncthreads();

            const uint32_t* Bsm = (const uint32_t*)(smem + (buf ? SM_B1 : SM_B0));

            float acc[2][8][4];
#pragma unroll
            for (int mi = 0; mi < 2; mi++)
#pragma unroll
                for (int nj = 0; nj < 8; nj++)
#pragma unroll
                    for (int r = 0; r < 4; r++) acc[mi][nj][r] = 0.0f;

#pragma unroll
            for (int s = 0; s < 16; s++) {
                uint4 a0 = *(const uint4*)(Asm + ((2 * warp_m + 0) * 16 + s) * 128 + ((lane * 4) ^ ((s & 3) << 2)));
                uint4 a1 = *(const uint4*)(Asm + ((2 * warp_m + 1) * 16 + s) * 128 + ((lane * 4) ^ ((s & 3) << 2)));
                uint2 bf[8];
#pragma unroll
                for (int nj = 0; nj < 8; nj++)
                    bf[nj] = *(const uint2*)(Bsm + ((8 * warp_n + nj) * 16 + s) * 64 + ((lane * 2) ^ ((s & 3) << 1)));
#pragma unroll
                for (int nj = 0; nj < 8; nj++) {
                    MMA_BF16(acc[0][nj], a0, bf[nj]);
                    MMA_BF16(acc[1][nj], a1, bf[nj]);
                }
            }

            if (pass == 0) {
                /* branch-free running min */
#pragma unroll
                for (int mi = 0; mi < 2; mi++)
#pragma unroll
                    for (int nj = 0; nj < 8; nj++) {
                        int colb = 64 * warp_n + 8 * nj + 2 * tq;
                        float e0 = Es[colb], e1 = Es[colb + 1];
                        runmin[2 * mi]     = fminf(runmin[2 * mi],     fmaf(-2.0f, acc[mi][nj][0], e0));
                        runmin[2 * mi]     = fminf(runmin[2 * mi],     fmaf(-2.0f, acc[mi][nj][1], e1));
                        runmin[2 * mi + 1] = fminf(runmin[2 * mi + 1], fmaf(-2.0f, acc[mi][nj][2], e0));
                        runmin[2 * mi + 1] = fminf(runmin[2 * mi + 1], fmaf(-2.0f, acc[mi][nj][3], e1));
                    }
            } else {
                /* rare margin hits -> global candidate append */
#pragma unroll
                for (int mi = 0; mi < 2; mi++)
#pragma unroll
                    for (int nj = 0; nj < 8; nj++) {
                        int colb = 64 * warp_n + 8 * nj + 2 * tq;
                        float e0 = Es[colb], e1 = Es[colb + 1];
                        float v0 = fmaf(-2.0f, acc[mi][nj][0], e0);
                        float v1 = fmaf(-2.0f, acc[mi][nj][1], e1);
                        float v2 = fmaf(-2.0f, acc[mi][nj][2], e0);
                        float v3 = fmaf(-2.0f, acc[mi][nj][3], e1);
                        int row0 = 32 * warp_m + 8 * (2 * mi) + ((2 * mi) >> 1) * 0; /* see map below */
                        (void)row0;
                        /* slot sl -> row = 32*warp_m + 16*(sl>>1) + 8*(sl&1) + g */
                        if (v0 <= thrv[2 * mi]) {
                            int tok = blockIdx.x * TQ + 32 * warp_m + 16 * mi + g;
                            int pos = atomicAdd(&g_ccnt[tok], 1);
                            if (pos < CAP_OUT) g_cand[tok * CAP_OUT + pos] = (unsigned short)(jt + colb);
                        }
                        if (v1 <= thrv[2 * mi]) {
                            int tok = blockIdx.x * TQ + 32 * warp_m + 16 * mi + g;
                            int pos = atomicAdd(&g_ccnt[tok], 1);
                            if (pos < CAP_OUT) g_cand[tok * CAP_OUT + pos] = (unsigned short)(jt + colb + 1);
                        }
                        if (v2 <= thrv[2 * mi + 1]) {
                            int tok = blockIdx.x * TQ + 32 * warp_m + 16 * mi + 8 + g;
                            int pos = atomicAdd(&g_ccnt[tok], 1);
                            if (pos < CAP_OUT) g_cand[tok * CAP_OUT + pos] = (unsigned short)(jt + colb);
                        }
                        if (v3 <= thrv[2 * mi + 1]) {
                            int tok = blockIdx.x * TQ + 32 * warp_m + 16 * mi + 8 + g;
                            int pos = atomicAdd(&g_ccnt[tok], 1);
                            if (pos < CAP_OUT) g_cand[tok * CAP_OUT + pos] = (unsigned short)(jt + colb + 1);
                        }
                    }
            }
            __syncthreads();
            buf ^= 1;
        }

        if (pass == 0) {
            /* merge mins: quad shuffle over tq, cross-warp smem atomicMin */
            /* sl -> row: sl = 2*mi + r, row = 32*warp_m + 16*mi + 8*r + g  */
#pragma unroll
            for (int sl = 0; sl < 4; sl++) {
                float m_ = runmin[sl];
                m_ = fminf(m_, __shfl_xor_sync(0xffffffffu, m_, 1));
                m_ = fminf(m_, __shfl_xor_sync(0xffffffffu, m_, 2));
                int row = 32 * warp_m + 16 * (sl >> 1) + 8 * (sl & 1) + g;
                if (tq == 0) atomicMin(rowmin + row, fkey(m_));
            }
            __syncthreads();
#pragma unroll
            for (int sl = 0; sl < 4; sl++) {
                int row = 32 * warp_m + 16 * (sl >> 1) + 8 * (sl & 1) + g;
                thrv[sl] = funkey(rowmin[row]) + MARGIN;
            }
        }
    }
}

/* ------------------------------------------------------------------ */
/* Rescore phase A: one thread per (token, candidate); arithmetic       */
/* byte-identical to the validated sequential-k version. Winner via    */
/* atomicMin on (fkey(d)<<32)|idx == same min/first-index tie rule.    */
__global__ void rescoreA_kernel(const float* __restrict__ z, const float* __restrict__ e) {
    int gid = blockIdx.x * 256 + threadIdx.x;
    int t = gid >> 3, c = gid & 7;
    int cnt = g_ccnt[t];
    if (cnt < 2 || cnt > CAP_OUT || c >= cnt) return;

    const float* zr = z + (size_t)t * CDIM;
    float Z = 0.0f;
#pragma unroll 8
    for (int k = 0; k < CDIM; k++) Z = __fmaf_rn(zr[k], zr[k], Z);

    int idx = g_cand[t * CAP_OUT + c];
    const float* er = e + (size_t)idx * CDIM;
    float dot = 0.0f;
#pragma unroll 8
    for (int k = 0; k < CDIM; k++) dot = __fmaf_rn(zr[k], er[k], dot);
    float d = __fadd_rn(__fmaf_rn(-2.0f, dot, Z), g_enorm[idx]);

    unsigned long long key = ((unsigned long long)fkey(d) << 32) | (unsigned)idx;
    atomicMin(&g_key[t], key);
}

/* Rescore phase B: winner / fast path / rare full-scan fallback. */
__global__ void rescoreB_kernel(const float* __restrict__ z, const float* __restrict__ e,
                                float* __restrict__ out_idx_f) {
    int t = blockIdx.x * 256 + threadIdx.x;
    if (t >= NTOK) return;
    int cnt = g_ccnt[t];
    int bi;
    if (cnt == 1) {
        bi = g_cand[t * CAP_OUT];
    } else if (cnt >= 2 && cnt <= CAP_OUT) {
        bi = (int)(unsigned)(g_key[t] & 0xFFFFFFFFull);
    } else {        /* overflow fallback: exact scan of all codes */
        const float* zr = z + (size_t)t * CDIM;
        float Z = 0.0f;
#pragma unroll 8
        for (int k = 0; k < CDIM; k++) Z = __fmaf_rn(zr[k], zr[k], Z);
        float bd = 3.4e38f; bi = 0;
        for (int idx = 0; idx < NCODES; idx++) {
            const float* er = e + (size_t)idx * CDIM;
            float dot = 0.0f;
#pragma unroll 8
            for (int k = 0; k < CDIM; k++) dot = __fmaf_rn(zr[k], er[k], dot);
            float d = __fadd_rn(__fmaf_rn(-2.0f, dot, Z), g_enorm[idx]);
            if (d < bd) { bd = d; bi = idx; }
        }
    }
    g_idx[t] = bi;
    out_idx_f[t] = (float)bi;
}

/* ------------------------------------------------------------------ */
__global__ void gather_kernel(const float* __restrict__ z,
                              const int* __restrict__ mask,
                              const float* __restrict__ e,
                              float* __restrict__ out) {
    __shared__ float s_loss[8];
    __shared__ int   s_valid[8];
    int wid  = threadIdx.x >> 5;
    int lane = threadIdx.x & 31;
    int t    = blockIdx.x * 8 + wid;

    int mk  = mask[t];
    int idx = g_idx[t];
    const float4* zr = (const float4*)(z + (size_t)t * CDIM);
    const float4* er = (const float4*)(e + (size_t)idx * CDIM);
    float4* o1 = (float4*)(out + (size_t)t * CDIM);
    float4* o2 = (float4*)(out + (size_t)NC_OUT + (size_t)t * CDIM);

    float ls = 0.0f;
#pragma unroll
    for (int i = 0; i < 2; i++) {
        int c = lane + 32 * i;
        float4 ev = er[c];
        float4 zv = zr[c];
        float4 q;
        if (mk) {
            q = ev;
            float dx = ev.x - zv.x, dy = ev.y - zv.y;
            float dz = ev.z - zv.z, dw = ev.w - zv.w;
            ls += dx * dx + dy * dy + dz * dz + dw * dw;
        } else {
            q = make_float4(0.0f, 0.0f, 0.0f, 0.0f);
        }
        o1[c] = q;
        o2[c] = q;
    }
#pragma unroll
    for (int o = 16; o; o >>= 1) ls += __shfl_down_sync(0xffffffffu, ls, o);
    if (lane == 0) {
        s_loss[wid]  = ls;
        s_valid[wid] = mk;
        if (mk) atomicAdd(&g_counts[idx], 1);
    }
    __syncthreads();
    if (threadIdx.x == 0) {
        float tot = 0.0f; int v = 0;
#pragma unroll
        for (int w = 0; w < 8; w++) { tot += s_loss[w]; v += s_valid[w]; }
        atomicAdd(&g_loss, tot);
        atomicAdd(&g_valid, v);
    }
}

/* ------------------------------------------------------------------ */
__global__ void finalize_kernel(float* __restrict__ out) {
    __shared__ float red[256];
    int tid = threadIdx.x;
    float nv    = (float)g_valid;
    float denom = nv + 1e-8f;
    float ent = 0.0f;
    for (int i = tid; i < NCODES; i += 256) {
        float p = (float)g_counts[i] / denom;
        ent += p * logf(p + 1e-8f);
    }
    red[tid] = ent;
    __syncthreads();
    for (int s = 128; s; s >>= 1) {
        if (tid < s) red[tid] += red[tid + s];
        __syncthreads();
    }
    if (tid == 0) {
        float valid = fmaxf(nv, 1.0f);
        float loss  = g_loss / valid;
        float* o = out + 2 * (size_t)NC_OUT + NTOK;
        o[0] = loss * 1.25f;
        o[1] = loss;
        o[2] = loss;
        o[3] = expf(-red[0]);
    }
}

/* ------------------------------------------------------------------ */
extern "C" void kernel_launch(void* const* d_in, const int* in_sizes, int n_in,
                              void* d_out, int out_size) {
    const float* z    = (const float*)d_in[0];
    const int*   mask = (const int*)d_in[1];
    const float* e    = (const float*)d_in[2];
    float*       out  = (float*)d_out;

    cudaFuncSetAttribute(cand_kernel,
                         cudaFuncAttributeMaxDynamicSharedMemorySize, SM_TOT);

    zero_kernel<<<NTOK / 256, 256>>>();
    enorm_kernel<<<NCODES / 8, 256>>>(e);
    eperm_kernel<<<NCODES * 128 / 256, 256>>>(e);
    zperm_kernel<<<NTOK * 128 / 256, 256>>>(z);
    cand_kernel<<<NTOK / TQ, 256, SM_TOT>>>();
    rescoreA_kernel<<<NTOK * CAP_OUT / 256, 256>>>(z, e);
    rescoreB_kernel<<<NTOK / 256, 256>>>(z, e, out + 2 * (size_t)NC_OUT);
    gather_kernel<<<NTOK / 8, 256>>>(z, mask, e, out);
    finalize_kernel<<<1, 256>>>(out);
}

// round 12
// speedup vs baseline: 5.0463x; 1.0969x over previous
#include <cuda_runtime.h>
#include <cuda_bf16.h>
#include <cstdint>
#include <math.h>

#define NCODES 4096
#define CDIM   256
#define NTOK   32768
#define NC_OUT (NTOK * CDIM)

#define TQ      128              /* tokens per CTA           */
#define TNC     128              /* codes per tile           */
#define NTILES  (NCODES / TNC)   /* 32                       */
#define MARGIN  4e-4f

#define TILE_U32 16384           /* 64 KB per permuted tile  */

/* cand smem layout (bytes): A 64K | B0 64K | B1 64K | Es | tileMin */
#define SM_A      0
#define SM_B0     65536
#define SM_B1     131072
#define SM_ES     196608
#define SM_TMIN   197120         /* 128 x 32 u32 = 16 KB */
#define SM_TOT    213504

/* exact-kernel smem: e tile (128 x 257 f32) | enorm | z bufs */
#define EX_ESTRIDE 257
#define EX_E      0
#define EX_EN     131584
#define EX_Z      132096         /* 8 warps x 260 floats */
#define EX_TOT    140416

__device__ float          g_enorm[NCODES];
__device__ int            g_counts[NCODES];
__device__ float          g_loss;
__device__ int            g_valid;
__device__ int            g_idx[NTOK];
__device__ unsigned long long g_key[NTOK];
__device__ int            g_lcnt[NTILES];
__device__ unsigned short g_list[NTILES * NTOK];             /* 2 MB  */
__device__ uint32_t       g_eperm[NTILES * TILE_U32];        /* 2 MB  */
__device__ uint32_t       g_zperm[(NTOK / TQ) * TILE_U32];   /* 16 MB */

/* order-preserving float<->uint key */
__device__ __forceinline__ unsigned fkey(float f) {
    unsigned u = __float_as_uint(f);
    return (u & 0x80000000u) ? ~u : (u | 0x80000000u);
}
__device__ __forceinline__ float funkey(unsigned k) {
    return (k & 0x80000000u) ? __uint_as_float(k & 0x7fffffffu)
                             : __uint_as_float(~k);
}
__device__ __forceinline__ uint32_t smem_u32(const void* p) {
    uint32_t a;
    asm("{ .reg .u64 t; cvta.to.shared.u64 t, %1; cvt.u32.u64 %0, t; }" : "=r"(a) : "l"(p));
    return a;
}
#define CP_ASYNC16(dst, src) \
    asm volatile("cp.async.cg.shared.global [%0], [%1], 16;" :: "r"(dst), "l"(src) : "memory")
#define CP_COMMIT()  asm volatile("cp.async.commit_group;" ::: "memory")
#define CP_WAIT(n)   asm volatile("cp.async.wait_group %0;" :: "n"(n) : "memory")

#define MMA_BF16(c, av, bv)                                                     \
    asm volatile("mma.sync.aligned.m16n8k16.row.col.f32.bf16.bf16.f32 "         \
        "{%0,%1,%2,%3}, {%4,%5,%6,%7}, {%8,%9}, {%0,%1,%2,%3};"                 \
        : "+f"((c)[0]), "+f"((c)[1]), "+f"((c)[2]), "+f"((c)[3])                \
        : "r"((av).x), "r"((av).y), "r"((av).z), "r"((av).w),                   \
          "r"((bv).x), "r"((bv).y))

/* ------------------------------------------------------------------ */
__global__ void zero_kernel() {
    int i = blockIdx.x * 256 + threadIdx.x;
    if (i < NCODES) g_counts[i] = 0;
    if (i < NTOK)   g_key[i] = 0xFFFFFFFFFFFFFFFFull;
    if (i < NTILES) g_lcnt[i] = 0;
    if (i == 0) { g_loss = 0.0f; g_valid = 0; }
}

/* ------------------------------------------------------------------ */
__global__ void enorm_kernel(const float* __restrict__ e) {
    int warp = (blockIdx.x * blockDim.x + threadIdx.x) >> 5;
    int lane = threadIdx.x & 31;
    if (warp >= NCODES) return;
    const float* row = e + (size_t)warp * CDIM;
    float s = 0.0f;
#pragma unroll
    for (int i = 0; i < CDIM / 32; i++) { float v = row[lane + 32 * i]; s += v * v; }
#pragma unroll
    for (int o = 16; o; o >>= 1) s += __shfl_down_sync(0xffffffffu, s, o);
    if (lane == 0) g_enorm[warp] = s;
}

/* ------------------------------------------------------------------ */
/* Pre-permute codebook/tokens to bf16 fragment layout.                */
__global__ void eperm_kernel(const float* __restrict__ e) {
    int v  = blockIdx.x * 256 + threadIdx.x;        /* NCODES*128 pairs */
    int ng = v >> 7, kp = v & 127;
    float2 ev = *(const float2*)(e + (size_t)ng * CDIM + 2 * kp);
    __nv_bfloat162 h = __floats2bfloat162_rn(ev.x, ev.y);
    int tile = ng >> 7, n = ng & 127;
    int s = kp >> 3, kk = (2 * kp) & 15;
    int nt = n >> 3, nc = n & 7;
    int lanep = nc * 4 + ((kk >> 1) & 3);
    int reg   = kk >> 3;
    g_eperm[tile * TILE_U32 + (nt * 16 + s) * 64 + ((lanep * 2) ^ ((s & 3) << 1)) + reg]
        = *(unsigned*)&h;
}

__global__ void zperm_kernel(const float* __restrict__ z) {
    int v  = blockIdx.x * 256 + threadIdx.x;        /* NTOK*128 pairs */
    int mg = v >> 7, kp = v & 127;
    float2 zv = *(const float2*)(z + (size_t)mg * CDIM + 2 * kp);
    __nv_bfloat162 h = __floats2bfloat162_rn(zv.x, zv.y);
    int blk = mg >> 7, m = mg & 127;
    int s = kp >> 3, kk = (2 * kp) & 15;
    int mt = m >> 4, lr = m & 15;
    int lanep = (lr & 7) * 4 + ((kk >> 1) & 3);
    int reg   = (lr >> 3) + 2 * (kk >> 3);
    g_zperm[blk * TILE_U32 + (mt * 16 + s) * 128 + ((lanep * 4) ^ ((s & 3) << 2)) + reg]
        = *(unsigned*)&h;
}

/* ------------------------------------------------------------------ */
/* Single-pass bf16 mma.sync over all 32 tiles; tracks per-(token,     */
/* tile) min of et = e_norm - 2*dot_bf16. Flags tiles with             */
/* tileMin <= rowMin + MARGIN into per-tile token lists. Margin proof  */
/* (rounds 8-10): any code achieving the exact reference argmin has    */
/* et <= et_min + MARGIN, so its tile is flagged.                      */
__global__ void __launch_bounds__(256, 1)
cand_kernel() {
    extern __shared__ char smem[];
    uint32_t* Asm     = (uint32_t*)(smem + SM_A);
    float*    Es      = (float*)(smem + SM_ES);
    unsigned* tileMin = (unsigned*)(smem + SM_TMIN);   /* [128][32] */
    const uint32_t sbase = smem_u32(smem);

    const int tid    = threadIdx.x;
    const int lane   = tid & 31;
    const int wid    = tid >> 5;
    const int warp_m = wid >> 1;
    const int warp_n = wid & 1;
    const int g      = lane >> 2;
    const int tq     = lane & 3;

    for (int i = tid; i < TQ * NTILES; i += 256) tileMin[i] = 0xFFFFFFFFu;

    /* A tile via cp.async (resident all tiles) */
    {
        const uint32_t* Ag = g_zperm + (size_t)blockIdx.x * TILE_U32;
#pragma unroll
        for (int i = 0; i < 16; i++) {
            int o = (i * 256 + tid) * 4;
            CP_ASYNC16(sbase + SM_A + o * 4, Ag + o);
        }
        CP_COMMIT();
    }
    /* B tile 0 */
    {
        const uint32_t* Bg = g_eperm;
#pragma unroll
        for (int i = 0; i < 16; i++) {
            int o = (i * 256 + tid) * 4;
            CP_ASYNC16(sbase + SM_B0 + o * 4, Bg + o);
        }
        CP_COMMIT();
    }

    int buf = 0;
#pragma unroll 1
    for (int tile = 0; tile < NTILES; tile++) {
        const int jt = tile * TNC;
        if (tile + 1 < NTILES) {
            const uint32_t* Bg = g_eperm + (size_t)(tile + 1) * TILE_U32;
            uint32_t dstb = sbase + (buf ? SM_B0 : SM_B1);
#pragma unroll
            for (int i = 0; i < 16; i++) {
                int o = (i * 256 + tid) * 4;
                CP_ASYNC16(dstb + o * 4, Bg + o);
            }
            CP_COMMIT();
            CP_WAIT(1);
        } else {
            CP_WAIT(0);
        }
        if (tid < TNC) Es[tid] = g_enorm[jt + tid];
        __syncthreads();

        const uint32_t* Bsm = (const uint32_t*)(smem + (buf ? SM_B1 : SM_B0));

        float acc[2][8][4];
#pragma unroll
        for (int mi = 0; mi < 2; mi++)
#pragma unroll
            for (int nj = 0; nj < 8; nj++)
#pragma unroll
                for (int r = 0; r < 4; r++) acc[mi][nj][r] = 0.0f;

#pragma unroll
        for (int s = 0; s < 16; s++) {
            uint4 a0 = *(const uint4*)(Asm + ((2 * warp_m + 0) * 16 + s) * 128 + ((lane * 4) ^ ((s & 3) << 2)));
            uint4 a1 = *(const uint4*)(Asm + ((2 * warp_m + 1) * 16 + s) * 128 + ((lane * 4) ^ ((s & 3) << 2)));
            uint2 bf[8];
#pragma unroll
            for (int nj = 0; nj < 8; nj++)
                bf[nj] = *(const uint2*)(Bsm + ((8 * warp_n + nj) * 16 + s) * 64 + ((lane * 2) ^ ((s & 3) << 1)));
#pragma unroll
            for (int nj = 0; nj < 8; nj++) {
                MMA_BF16(acc[0][nj], a0, bf[nj]);
                MMA_BF16(acc[1][nj], a1, bf[nj]);
            }
        }

        /* per-tile min: slot sl=2*mi+r -> row 32*warp_m + 16*mi + 8*r + g */
        float tmin[4] = {3.4e38f, 3.4e38f, 3.4e38f, 3.4e38f};
#pragma unroll
        for (int mi = 0; mi < 2; mi++)
#pragma unroll
            for (int nj = 0; nj < 8; nj++) {
                int colb = 64 * warp_n + 8 * nj + 2 * tq;
                float e0 = Es[colb], e1 = Es[colb + 1];
                tmin[2 * mi]     = fminf(tmin[2 * mi],     fmaf(-2.0f, acc[mi][nj][0], e0));
                tmin[2 * mi]     = fminf(tmin[2 * mi],     fmaf(-2.0f, acc[mi][nj][1], e1));
                tmin[2 * mi + 1] = fminf(tmin[2 * mi + 1], fmaf(-2.0f, acc[mi][nj][2], e0));
                tmin[2 * mi + 1] = fminf(tmin[2 * mi + 1], fmaf(-2.0f, acc[mi][nj][3], e1));
            }
#pragma unroll
        for (int sl = 0; sl < 4; sl++) {
            float m_ = tmin[sl];
            m_ = fminf(m_, __shfl_xor_sync(0xffffffffu, m_, 1));
            m_ = fminf(m_, __shfl_xor_sync(0xffffffffu, m_, 2));
            if (tq == 0) {
                int row = 32 * warp_m + 16 * (sl >> 1) + 8 * (sl & 1) + g;
                atomicMin(tileMin + row * NTILES + tile, fkey(m_));
            }
        }
        __syncthreads();
        buf ^= 1;
    }

    /* flag tiles per token; append token to per-tile global lists */
    if (tid < TQ) {
        int row = tid;
        int tok = blockIdx.x * TQ + row;
        unsigned mk = 0xFFFFFFFFu;
#pragma unroll
        for (int t = 0; t < NTILES; t++)
            mk = min(mk, tileMin[row * NTILES + t]);
        float thr = funkey(mk) + MARGIN;
#pragma unroll 1
        for (int t = 0; t < NTILES; t++) {
            if (funkey(tileMin[row * NTILES + t]) <= thr) {
                int pos = atomicAdd(&g_lcnt[t], 1);
                g_list[t * NTOK + pos] = (unsigned short)tok;
            }
        }
    }
}

/* ------------------------------------------------------------------ */
/* Exact kernel: for each flagged (token, tile), compute reference-    */
/* exact d = fl(fl(Z - 2*dot) + e_norm) for all 128 tile codes with    */
/* sequential-k fp32 chains (round-4-validated ordering); resolve      */
/* global winner via atomicMin on (fkey(d)<<32)|idx (= reference min   */
/* + first-index tie rule). Covers ties: all tie-achievers flagged.    */
__global__ void __launch_bounds__(256, 1)
exact_kernel(const float* __restrict__ z, const float* __restrict__ e) {
    extern __shared__ char smem[];
    float* Esm  = (float*)(smem + EX_E);     /* [128][257] */
    float* ENsm = (float*)(smem + EX_EN);    /* [128]      */
    const int tile = blockIdx.y;
    const int spl  = blockIdx.x;             /* 0..7 */
    const int tid  = threadIdx.x;
    const int lane = tid & 31;
    const int wid  = tid >> 5;
    float* zbuf = (float*)(smem + EX_Z) + wid * 260;

    /* stage tile codes fp32 into padded smem */
    {
        const float* eb = e + (size_t)tile * TNC * CDIM;
        for (int i = tid; i < TNC * CDIM; i += 256) {
            int c = i >> 8, k = i & 255;
            Esm[c * EX_ESTRIDE + k] = eb[i];
        }
        if (tid < TNC) ENsm[tid] = g_enorm[tile * TNC + tid];
    }
    __syncthreads();

    const int L    = g_lcnt[tile];
    const int slot = spl * 8 + wid;          /* 0..63, stride 64 */

    for (int i = slot; i < L; i += 64) {
        int tok = g_list[tile * NTOK + i];
        /* warp loads z row to its smem buffer */
        {
            const float4* zr = (const float4*)(z + (size_t)tok * CDIM);
            ((float4*)zbuf)[lane]      = zr[lane];
            ((float4*)zbuf)[lane + 32] = zr[lane + 32];
        }
        __syncwarp();

        /* 5 interleaved sequential fp32 chains: Z + 4 code dots       */
        /* lane l owns codes {l, l+32, l+64, l+96}: bank (l+k)%32 CF   */
        float Zc = 0.0f, d0 = 0.0f, d1 = 0.0f, d2 = 0.0f, d3 = 0.0f;
        const float* e0p = Esm + (lane +  0) * EX_ESTRIDE;
        const float* e1p = Esm + (lane + 32) * EX_ESTRIDE;
        const float* e2p = Esm + (lane + 64) * EX_ESTRIDE;
        const float* e3p = Esm + (lane + 96) * EX_ESTRIDE;
#pragma unroll 8
        for (int k = 0; k < CDIM; k++) {
            float zv = zbuf[k];
            Zc = __fmaf_rn(zv, zv, Zc);
            d0 = __fmaf_rn(zv, e0p[k], d0);
            d1 = __fmaf_rn(zv, e1p[k], d1);
            d2 = __fmaf_rn(zv, e2p[k], d2);
            d3 = __fmaf_rn(zv, e3p[k], d3);
        }
        float v0 = __fadd_rn(__fmaf_rn(-2.0f, d0, Zc), ENsm[lane]);
        float v1 = __fadd_rn(__fmaf_rn(-2.0f, d1, Zc), ENsm[lane + 32]);
        float v2 = __fadd_rn(__fmaf_rn(-2.0f, d2, Zc), ENsm[lane + 64]);
        float v3 = __fadd_rn(__fmaf_rn(-2.0f, d3, Zc), ENsm[lane + 96]);

        int base = tile * TNC + lane;
        unsigned long long key =       ((unsigned long long)fkey(v0) << 32) | (unsigned)(base);
        key = min(key, ((unsigned long long)fkey(v1) << 32) | (unsigned)(base + 32));
        key = min(key, ((unsigned long long)fkey(v2) << 32) | (unsigned)(base + 64));
        key = min(key, ((unsigned long long)fkey(v3) << 32) | (unsigned)(base + 96));
#pragma unroll
        for (int o = 16; o; o >>= 1) {
            unsigned long long ok = __shfl_xor_sync(0xffffffffu, key, o);
            key = min(key, ok);
        }
        if (lane == 0) atomicMin(&g_key[tok], key);
        __syncwarp();
    }
}

/* ------------------------------------------------------------------ */
__global__ void keyidx_kernel(float* __restrict__ out_idx_f) {
    int t = blockIdx.x * 256 + threadIdx.x;
    if (t >= NTOK) return;
    int bi = (int)(unsigned)(g_key[t] & 0xFFFFFFFFull);
    g_idx[t] = bi;
    out_idx_f[t] = (float)bi;
}

/* ------------------------------------------------------------------ */
__global__ void gather_kernel(const float* __restrict__ z,
                              const int* __restrict__ mask,
                              const float* __restrict__ e,
                              float* __restrict__ out) {
    __shared__ float s_loss[8];
    __shared__ int   s_valid[8];
    int wid  = threadIdx.x >> 5;
    int lane = threadIdx.x & 31;
    int t    = blockIdx.x * 8 + wid;

    int mk  = mask[t];
    int idx = g_idx[t];
    const float4* zr = (const float4*)(z + (size_t)t * CDIM);
    const float4* er = (const float4*)(e + (size_t)idx * CDIM);
    float4* o1 = (float4*)(out + (size_t)t * CDIM);
    float4* o2 = (float4*)(out + (size_t)NC_OUT + (size_t)t * CDIM);

    float ls = 0.0f;
#pragma unroll
    for (int i = 0; i < 2; i++) {
        int c = lane + 32 * i;
        float4 ev = er[c];
        float4 zv = zr[c];
        float4 q;
        if (mk) {
            q = ev;
            float dx = ev.x - zv.x, dy = ev.y - zv.y;
            float dz = ev.z - zv.z, dw = ev.w - zv.w;
            ls += dx * dx + dy * dy + dz * dz + dw * dw;
        } else {
            q = make_float4(0.0f, 0.0f, 0.0f, 0.0f);
        }
        o1[c] = q;
        o2[c] = q;
    }
#pragma unroll
    for (int o = 16; o; o >>= 1) ls += __shfl_down_sync(0xffffffffu, ls, o);
    if (lane == 0) {
        s_loss[wid]  = ls;
        s_valid[wid] = mk;
        if (mk) atomicAdd(&g_counts[idx], 1);
    }
    __syncthreads();
    if (threadIdx.x == 0) {
        float tot = 0.0f; int v = 0;
#pragma unroll
        for (int w = 0; w < 8; w++) { tot += s_loss[w]; v += s_valid[w]; }
        atomicAdd(&g_loss, tot);
        atomicAdd(&g_valid, v);
    }
}

/* ------------------------------------------------------------------ */
__global__ void finalize_kernel(float* __restrict__ out) {
    __shared__ float red[256];
    int tid = threadIdx.x;
    float nv    = (float)g_valid;
    float denom = nv + 1e-8f;
    float ent = 0.0f;
    for (int i = tid; i < NCODES; i += 256) {
        float p = (float)g_counts[i] / denom;
        ent += p * logf(p + 1e-8f);
    }
    red[tid] = ent;
    __syncthreads();
    for (int s = 128; s; s >>= 1) {
        if (tid < s) red[tid] += red[tid + s];
        __syncthreads();
    }
    if (tid == 0) {
        float valid = fmaxf(nv, 1.0f);
        float loss  = g_loss / valid;
        float* o = out + 2 * (size_t)NC_OUT + NTOK;
        o[0] = loss * 1.25f;
        o[1] = loss;
        o[2] = loss;
        o[3] = expf(-red[0]);
    }
}

/* ------------------------------------------------------------------ */
extern "C" void kernel_launch(void* const* d_in, const int* in_sizes, int n_in,
                              void* d_out, int out_size) {
    const float* z    = (const float*)d_in[0];
    const int*   mask = (const int*)d_in[1];
    const float* e    = (const float*)d_in[2];
    float*       out  = (float*)d_out;

    cudaFuncSetAttribute(cand_kernel,
                         cudaFuncAttributeMaxDynamicSharedMemorySize, SM_TOT);
    cudaFuncSetAttribute(exact_kernel,
                         cudaFuncAttributeMaxDynamicSharedMemorySize, EX_TOT);

    zero_kernel<<<NTOK / 256, 256>>>();
    enorm_kernel<<<NCODES / 8, 256>>>(e);
    eperm_kernel<<<NCODES * 128 / 256, 256>>>(e);
    zperm_kernel<<<NTOK * 128 / 256, 256>>>(z);
    cand_kernel<<<NTOK / TQ, 256, SM_TOT>>>();
    exact_kernel<<<dim3(8, NTILES), 256, EX_TOT>>>(z, e);
    keyidx_kernel<<<NTOK / 256, 256>>>(out + 2 * (size_t)NC_OUT);
    gather_kernel<<<NTOK / 8, 256>>>(z, mask, e, out);
    finalize_kernel<<<1, 256>>>(out);
}

// round 13
// speedup vs baseline: 5.0658x; 1.0039x over previous
#include <cuda_runtime.h>
#include <cuda_bf16.h>
#include <cstdint>
#include <math.h>

#define NCODES 4096
#define CDIM   256
#define NTOK   32768
#define NC_OUT (NTOK * CDIM)

#define TQ      128              /* tokens per CTA           */
#define TNC     128              /* codes per tile           */
#define NTILES  (NCODES / TNC)   /* 32                       */
#define MARGIN  4e-4f

#define TILE_U32 16384           /* 64 KB per permuted tile  */

/* cand smem layout (bytes): A 64K | B0 64K | B1 64K | Es | tileMin */
#define SM_A      0
#define SM_B0     65536
#define SM_B1     131072
#define SM_ES     196608
#define SM_TMIN   197120         /* 32 x 128 u32 = 16 KB (tile-major) */
#define SM_TOT    213504

/* exact-kernel smem: e tile (128 x 257 f32) | enorm | z bufs */
#define EX_ESTRIDE 257
#define EX_E      0
#define EX_EN     131584
#define EX_Z      132096         /* 8 warps x 260 floats */
#define EX_TOT    140416
#define EX_SPL    4              /* splits per tile (grid 4 x 32 = 128) */

__device__ float          g_enorm[NCODES];
__device__ int            g_counts[NCODES];
__device__ float          g_loss;
__device__ int            g_valid;
__device__ int            g_idx[NTOK];
__device__ unsigned long long g_key[NTOK];
__device__ int            g_lcnt[NTILES];
__device__ unsigned short g_list[NTILES * NTOK];             /* 2 MB  */
__device__ uint32_t       g_eperm[NTILES * TILE_U32];        /* 2 MB  */
__device__ uint32_t       g_zperm[(NTOK / TQ) * TILE_U32];   /* 16 MB */

/* order-preserving float<->uint key */
__device__ __forceinline__ unsigned fkey(float f) {
    unsigned u = __float_as_uint(f);
    return (u & 0x80000000u) ? ~u : (u | 0x80000000u);
}
__device__ __forceinline__ float funkey(unsigned k) {
    return (k & 0x80000000u) ? __uint_as_float(k & 0x7fffffffu)
                             : __uint_as_float(~k);
}
__device__ __forceinline__ uint32_t smem_u32(const void* p) {
    uint32_t a;
    asm("{ .reg .u64 t; cvta.to.shared.u64 t, %1; cvt.u32.u64 %0, t; }" : "=r"(a) : "l"(p));
    return a;
}
#define CP_ASYNC16(dst, src) \
    asm volatile("cp.async.cg.shared.global [%0], [%1], 16;" :: "r"(dst), "l"(src) : "memory")
#define CP_COMMIT()  asm volatile("cp.async.commit_group;" ::: "memory")
#define CP_WAIT(n)   asm volatile("cp.async.wait_group %0;" :: "n"(n) : "memory")

#define MMA_BF16(c, av, bv)                                                     \
    asm volatile("mma.sync.aligned.m16n8k16.row.col.f32.bf16.bf16.f32 "         \
        "{%0,%1,%2,%3}, {%4,%5,%6,%7}, {%8,%9}, {%0,%1,%2,%3};"                 \
        : "+f"((c)[0]), "+f"((c)[1]), "+f"((c)[2]), "+f"((c)[3])                \
        : "r"((av).x), "r"((av).y), "r"((av).z), "r"((av).w),                   \
          "r"((bv).x), "r"((bv).y))

/* ------------------------------------------------------------------ */
__global__ void zero_kernel() {
    int i = blockIdx.x * 256 + threadIdx.x;
    if (i < NCODES) g_counts[i] = 0;
    if (i < NTOK)   g_key[i] = 0xFFFFFFFFFFFFFFFFull;
    if (i < NTILES) g_lcnt[i] = 0;
    if (i == 0) { g_loss = 0.0f; g_valid = 0; }
}

/* ------------------------------------------------------------------ */
__global__ void enorm_kernel(const float* __restrict__ e) {
    int warp = (blockIdx.x * blockDim.x + threadIdx.x) >> 5;
    int lane = threadIdx.x & 31;
    if (warp >= NCODES) return;
    const float* row = e + (size_t)warp * CDIM;
    float s = 0.0f;
#pragma unroll
    for (int i = 0; i < CDIM / 32; i++) { float v = row[lane + 32 * i]; s += v * v; }
#pragma unroll
    for (int o = 16; o; o >>= 1) s += __shfl_down_sync(0xffffffffu, s, o);
    if (lane == 0) g_enorm[warp] = s;
}

/* ------------------------------------------------------------------ */
/* Pre-permute codebook/tokens to bf16 fragment layout.                */
__global__ void eperm_kernel(const float* __restrict__ e) {
    int v  = blockIdx.x * 256 + threadIdx.x;        /* NCODES*128 pairs */
    int ng = v >> 7, kp = v & 127;
    float2 ev = *(const float2*)(e + (size_t)ng * CDIM + 2 * kp);
    __nv_bfloat162 h = __floats2bfloat162_rn(ev.x, ev.y);
    int tile = ng >> 7, n = ng & 127;
    int s = kp >> 3, kk = (2 * kp) & 15;
    int nt = n >> 3, nc = n & 7;
    int lanep = nc * 4 + ((kk >> 1) & 3);
    int reg   = kk >> 3;
    g_eperm[tile * TILE_U32 + (nt * 16 + s) * 64 + ((lanep * 2) ^ ((s & 3) << 1)) + reg]
        = *(unsigned*)&h;
}

__global__ void zperm_kernel(const float* __restrict__ z) {
    int v  = blockIdx.x * 256 + threadIdx.x;        /* NTOK*128 pairs */
    int mg = v >> 7, kp = v & 127;
    float2 zv = *(const float2*)(z + (size_t)mg * CDIM + 2 * kp);
    __nv_bfloat162 h = __floats2bfloat162_rn(zv.x, zv.y);
    int blk = mg >> 7, m = mg & 127;
    int s = kp >> 3, kk = (2 * kp) & 15;
    int mt = m >> 4, lr = m & 15;
    int lanep = (lr & 7) * 4 + ((kk >> 1) & 3);
    int reg   = (lr >> 3) + 2 * (kk >> 3);
    g_zperm[blk * TILE_U32 + (mt * 16 + s) * 128 + ((lanep * 4) ^ ((s & 3) << 2)) + reg]
        = *(unsigned*)&h;
}

/* ------------------------------------------------------------------ */
/* Single-pass bf16 mma.sync over all 32 tiles; tracks per-(token,     */
/* tile) min of et = e_norm - 2*dot_bf16 in tile-major smem (bank-     */
/* conflict-free atomics). Flags tiles with tileMin <= rowMin + MARGIN */
/* into per-tile token lists. Margin proof (rounds 8-10): any code     */
/* achieving the exact reference argmin has et <= et_min + MARGIN.     */
__global__ void __launch_bounds__(256, 1)
cand_kernel() {
    extern __shared__ char smem[];
    uint32_t* Asm     = (uint32_t*)(smem + SM_A);
    float*    Es      = (float*)(smem + SM_ES);
    unsigned* tileMin = (unsigned*)(smem + SM_TMIN);   /* [32][128] tile-major */
    const uint32_t sbase = smem_u32(smem);

    const int tid    = threadIdx.x;
    const int lane   = tid & 31;
    const int wid    = tid >> 5;
    const int warp_m = wid >> 1;
    const int warp_n = wid & 1;
    const int g      = lane >> 2;
    const int tq     = lane & 3;

    for (int i = tid; i < TQ * NTILES; i += 256) tileMin[i] = 0xFFFFFFFFu;

    /* A tile via cp.async (resident all tiles) */
    {
        const uint32_t* Ag = g_zperm + (size_t)blockIdx.x * TILE_U32;
#pragma unroll
        for (int i = 0; i < 16; i++) {
            int o = (i * 256 + tid) * 4;
            CP_ASYNC16(sbase + SM_A + o * 4, Ag + o);
        }
        CP_COMMIT();
    }
    /* B tile 0 */
    {
        const uint32_t* Bg = g_eperm;
#pragma unroll
        for (int i = 0; i < 16; i++) {
            int o = (i * 256 + tid) * 4;
            CP_ASYNC16(sbase + SM_B0 + o * 4, Bg + o);
        }
        CP_COMMIT();
    }

    int buf = 0;
#pragma unroll 1
    for (int tile = 0; tile < NTILES; tile++) {
        const int jt = tile * TNC;
        if (tile + 1 < NTILES) {
            const uint32_t* Bg = g_eperm + (size_t)(tile + 1) * TILE_U32;
            uint32_t dstb = sbase + (buf ? SM_B0 : SM_B1);
#pragma unroll
            for (int i = 0; i < 16; i++) {
                int o = (i * 256 + tid) * 4;
                CP_ASYNC16(dstb + o * 4, Bg + o);
            }
            CP_COMMIT();
            CP_WAIT(1);
        } else {
            CP_WAIT(0);
        }
        if (tid < TNC) Es[tid] = g_enorm[jt + tid];
        __syncthreads();

        const uint32_t* Bsm = (const uint32_t*)(smem + (buf ? SM_B1 : SM_B0));

        float acc[2][8][4];
#pragma unroll
        for (int mi = 0; mi < 2; mi++)
#pragma unroll
            for (int nj = 0; nj < 8; nj++)
#pragma unroll
                for (int r = 0; r < 4; r++) acc[mi][nj][r] = 0.0f;

#pragma unroll
        for (int s = 0; s < 16; s++) {
            uint4 a0 = *(const uint4*)(Asm + ((2 * warp_m + 0) * 16 + s) * 128 + ((lane * 4) ^ ((s & 3) << 2)));
            uint4 a1 = *(const uint4*)(Asm + ((2 * warp_m + 1) * 16 + s) * 128 + ((lane * 4) ^ ((s & 3) << 2)));
            uint2 bf[8];
#pragma unroll
            for (int nj = 0; nj < 8; nj++)
                bf[nj] = *(const uint2*)(Bsm + ((8 * warp_n + nj) * 16 + s) * 64 + ((lane * 2) ^ ((s & 3) << 1)));
#pragma unroll
            for (int nj = 0; nj < 8; nj++) {
                MMA_BF16(acc[0][nj], a0, bf[nj]);
                MMA_BF16(acc[1][nj], a1, bf[nj]);
            }
        }

        /* per-tile min: slot sl=2*mi+r -> row 32*warp_m + 16*mi + 8*r + g */
        float tmin[4] = {3.4e38f, 3.4e38f, 3.4e38f, 3.4e38f};
#pragma unroll
        for (int mi = 0; mi < 2; mi++)
#pragma unroll
            for (int nj = 0; nj < 8; nj++) {
                int colb = 64 * warp_n + 8 * nj + 2 * tq;
                float e0 = Es[colb], e1 = Es[colb + 1];
                tmin[2 * mi]     = fminf(tmin[2 * mi],     fmaf(-2.0f, acc[mi][nj][0], e0));
                tmin[2 * mi]     = fminf(tmin[2 * mi],     fmaf(-2.0f, acc[mi][nj][1], e1));
                tmin[2 * mi + 1] = fminf(tmin[2 * mi + 1], fmaf(-2.0f, acc[mi][nj][2], e0));
                tmin[2 * mi + 1] = fminf(tmin[2 * mi + 1], fmaf(-2.0f, acc[mi][nj][3], e1));
            }
#pragma unroll
        for (int sl = 0; sl < 4; sl++) {
            float m_ = tmin[sl];
            m_ = fminf(m_, __shfl_xor_sync(0xffffffffu, m_, 1));
            m_ = fminf(m_, __shfl_xor_sync(0xffffffffu, m_, 2));
            if (tq == 0) {
                int row = 32 * warp_m + 16 * (sl >> 1) + 8 * (sl & 1) + g;
                /* tile-major: lanes g=0..7 hit distinct banks */
                atomicMin(tileMin + tile * TQ + row, fkey(m_));
            }
        }
        __syncthreads();
        buf ^= 1;
    }

    /* flag tiles per token (key-space compares); append to tile lists */
    if (tid < TQ) {
        int row = tid;
        int tok = blockIdx.x * TQ + row;
        unsigned mk = 0xFFFFFFFFu;
#pragma unroll
        for (int t = 0; t < NTILES; t++)
            mk = min(mk, tileMin[t * TQ + row]);
        unsigned thr_key = fkey(funkey(mk) + MARGIN);
#pragma unroll 1
        for (int t = 0; t < NTILES; t++) {
            if (tileMin[t * TQ + row] <= thr_key) {
                int pos = atomicAdd(&g_lcnt[t], 1);
                g_list[t * NTOK + pos] = (unsigned short)tok;
            }
        }
    }
}

/* ------------------------------------------------------------------ */
/* Exact kernel: for each flagged (token, tile), compute reference-    */
/* exact d = fl(fl(Z - 2*dot) + e_norm) for all 128 tile codes with    */
/* sequential-k fp32 chains (round-4-validated ordering); resolve      */
/* global winner via atomicMin on (fkey(d)<<32)|idx (= reference min   */
/* + first-index tie rule). Covers ties: all tie-achievers flagged.    */
__global__ void __launch_bounds__(256, 1)
exact_kernel(const float* __restrict__ z, const float* __restrict__ e) {
    extern __shared__ char smem[];
    float* Esm  = (float*)(smem + EX_E);     /* [128][257] */
    float* ENsm = (float*)(smem + EX_EN);    /* [128]      */
    const int tile = blockIdx.y;
    const int spl  = blockIdx.x;             /* 0..EX_SPL-1 */
    const int tid  = threadIdx.x;
    const int lane = tid & 31;
    const int wid  = tid >> 5;
    float* zbuf = (float*)(smem + EX_Z) + wid * 260;

    /* stage tile codes fp32 into padded smem */
    {
        const float* eb = e + (size_t)tile * TNC * CDIM;
        for (int i = tid; i < TNC * CDIM; i += 256) {
            int c = i >> 8, k = i & 255;
            Esm[c * EX_ESTRIDE + k] = eb[i];
        }
        if (tid < TNC) ENsm[tid] = g_enorm[tile * TNC + tid];
    }
    __syncthreads();

    const int L    = g_lcnt[tile];
    const int slot = spl * 8 + wid;          /* 0..31, stride 32 */

    for (int i = slot; i < L; i += EX_SPL * 8) {
        int tok = g_list[tile * NTOK + i];
        /* warp loads z row to its smem buffer */
        {
            const float4* zr = (const float4*)(z + (size_t)tok * CDIM);
            ((float4*)zbuf)[lane]      = zr[lane];
            ((float4*)zbuf)[lane + 32] = zr[lane + 32];
        }
        __syncwarp();

        /* 5 interleaved sequential fp32 chains: Z + 4 code dots       */
        /* lane l owns codes {l, l+32, l+64, l+96}: bank (l+k)%32 CF   */
        float Zc = 0.0f, d0 = 0.0f, d1 = 0.0f, d2 = 0.0f, d3 = 0.0f;
        const float* e0p = Esm + (lane +  0) * EX_ESTRIDE;
        const float* e1p = Esm + (lane + 32) * EX_ESTRIDE;
        const float* e2p = Esm + (lane + 64) * EX_ESTRIDE;
        const float* e3p = Esm + (lane + 96) * EX_ESTRIDE;
#pragma unroll 8
        for (int k = 0; k < CDIM; k++) {
            float zv = zbuf[k];
            Zc = __fmaf_rn(zv, zv, Zc);
            d0 = __fmaf_rn(zv, e0p[k], d0);
            d1 = __fmaf_rn(zv, e1p[k], d1);
            d2 = __fmaf_rn(zv, e2p[k], d2);
            d3 = __fmaf_rn(zv, e3p[k], d3);
        }
        float v0 = __fadd_rn(__fmaf_rn(-2.0f, d0, Zc), ENsm[lane]);
        float v1 = __fadd_rn(__fmaf_rn(-2.0f, d1, Zc), ENsm[lane + 32]);
        float v2 = __fadd_rn(__fmaf_rn(-2.0f, d2, Zc), ENsm[lane + 64]);
        float v3 = __fadd_rn(__fmaf_rn(-2.0f, d3, Zc), ENsm[lane + 96]);

        int base = tile * TNC + lane;
        unsigned long long key =       ((unsigned long long)fkey(v0) << 32) | (unsigned)(base);
        key = min(key, ((unsigned long long)fkey(v1) << 32) | (unsigned)(base + 32));
        key = min(key, ((unsigned long long)fkey(v2) << 32) | (unsigned)(base + 64));
        key = min(key, ((unsigned long long)fkey(v3) << 32) | (unsigned)(base + 96));
#pragma unroll
        for (int o = 16; o; o >>= 1) {
            unsigned long long ok = __shfl_xor_sync(0xffffffffu, key, o);
            key = min(key, ok);
        }
        if (lane == 0) atomicMin(&g_key[tok], key);
        __syncwarp();
    }
}

/* ------------------------------------------------------------------ */
__global__ void keyidx_kernel(float* __restrict__ out_idx_f) {
    int t = blockIdx.x * 256 + threadIdx.x;
    if (t >= NTOK) return;
    int bi = (int)(unsigned)(g_key[t] & 0xFFFFFFFFull);
    g_idx[t] = bi;
    out_idx_f[t] = (float)bi;
}

/* ------------------------------------------------------------------ */
__global__ void gather_kernel(const float* __restrict__ z,
                              const int* __restrict__ mask,
                              const float* __restrict__ e,
                              float* __restrict__ out) {
    __shared__ float s_loss[8];
    __shared__ int   s_valid[8];
    int wid  = threadIdx.x >> 5;
    int lane = threadIdx.x & 31;
    int t    = blockIdx.x * 8 + wid;

    int mk  = mask[t];
    int idx = g_idx[t];
    const float4* zr = (const float4*)(z + (size_t)t * CDIM);
    const float4* er = (const float4*)(e + (size_t)idx * CDIM);
    float4* o1 = (float4*)(out + (size_t)t * CDIM);
    float4* o2 = (float4*)(out + (size_t)NC_OUT + (size_t)t * CDIM);

    float ls = 0.0f;
#pragma unroll
    for (int i = 0; i < 2; i++) {
        int c = lane + 32 * i;
        float4 ev = er[c];
        float4 zv = zr[c];
        float4 q;
        if (mk) {
            q = ev;
            float dx = ev.x - zv.x, dy = ev.y - zv.y;
            float dz = ev.z - zv.z, dw = ev.w - zv.w;
            ls += dx * dx + dy * dy + dz * dz + dw * dw;
        } else {
            q = make_float4(0.0f, 0.0f, 0.0f, 0.0f);
        }
        o1[c] = q;
        o2[c] = q;
    }
#pragma unroll
    for (int o = 16; o; o >>= 1) ls += __shfl_down_sync(0xffffffffu, ls, o);
    if (lane == 0) {
        s_loss[wid]  = ls;
        s_valid[wid] = mk;
        if (mk) atomicAdd(&g_counts[idx], 1);
    }
    __syncthreads();
    if (threadIdx.x == 0) {
        float tot = 0.0f; int v = 0;
#pragma unroll
        for (int w = 0; w < 8; w++) { tot += s_loss[w]; v += s_valid[w]; }
        atomicAdd(&g_loss, tot);
        atomicAdd(&g_valid, v);
    }
}

/* ------------------------------------------------------------------ */
__global__ void finalize_kernel(float* __restrict__ out) {
    __shared__ float red[256];
    int tid = threadIdx.x;
    float nv    = (float)g_valid;
    float denom = nv + 1e-8f;
    float ent = 0.0f;
    for (int i = tid; i < NCODES; i += 256) {
        float p = (float)g_counts[i] / denom;
        ent += p * logf(p + 1e-8f);
    }
    red[tid] = ent;
    __syncthreads();
    for (int s = 128; s; s >>= 1) {
        if (tid < s) red[tid] += red[tid + s];
        __syncthreads();
    }
    if (tid == 0) {
        float valid = fmaxf(nv, 1.0f);
        float loss  = g_loss / valid;
        float* o = out + 2 * (size_t)NC_OUT + NTOK;
        o[0] = loss * 1.25f;
        o[1] = loss;
        o[2] = loss;
        o[3] = expf(-red[0]);
    }
}

/* ------------------------------------------------------------------ */
extern "C" void kernel_launch(void* const* d_in, const int* in_sizes, int n_in,
                              void* d_out, int out_size) {
    const float* z    = (const float*)d_in[0];
    const int*   mask = (const int*)d_in[1];
    const float* e    = (const float*)d_in[2];
    float*       out  = (float*)d_out;

    cudaFuncSetAttribute(cand_kernel,
                         cudaFuncAttributeMaxDynamicSharedMemorySize, SM_TOT);
    cudaFuncSetAttribute(exact_kernel,
                         cudaFuncAttributeMaxDynamicSharedMemorySize, EX_TOT);

    zero_kernel<<<NTOK / 256, 256>>>();
    enorm_kernel<<<NCODES / 8, 256>>>(e);
    eperm_kernel<<<NCODES * 128 / 256, 256>>>(e);
    zperm_kernel<<<NTOK * 128 / 256, 256>>>(z);
    cand_kernel<<<NTOK / TQ, 256, SM_TOT>>>();
    exact_kernel<<<dim3(EX_SPL, NTILES), 256, EX_TOT>>>(z, e);
    keyidx_kernel<<<NTOK / 256, 256>>>(out + 2 * (size_t)NC_OUT);
    gather_kernel<<<NTOK / 8, 256>>>(z, mask, e, out);
    finalize_kernel<<<1, 256>>>(out);
}

// round 14
// speedup vs baseline: 6.0379x; 1.1919x over previous
#include <cuda_runtime.h>
#include <cuda_bf16.h>
#include <cstdint>
#include <math.h>

#define NCODES 4096
#define CDIM   256
#define NTOK   32768
#define NC_OUT (NTOK * CDIM)

#define TQ      128              /* tokens per CTA           */
#define TNC     128              /* codes per tile           */
#define NTILES  (NCODES / TNC)   /* 32                       */
#define NSEC    (NTILES * 2)     /* 64 sectors of 64 codes   */
#define MARGIN  4e-4f

#define TILE_U32 16384           /* 64 KB per permuted tile  */

/* cand smem layout (bytes): A 64K | B0 64K | B1 64K | Es | secMin */
#define SM_A      0
#define SM_B0     65536
#define SM_B1     131072
#define SM_ES     196608
#define SM_SMIN   197120         /* 64 x 128 u32 = 32 KB (sector-major) */
#define SM_TOT    229888         /* < 227 KiB cap */

/* exact-kernel smem: e sector (64 x 257 f32) | enorm | z bufs */
#define EX_ESTRIDE 257
#define EX_E      0
#define EX_EN     65792
#define EX_Z      66048          /* 8 warps x 260 floats */
#define EX_TOT    74368
#define EX_SPL    2              /* grid 2 x 64 = 128 CTAs */

__device__ float          g_enorm[NCODES];
__device__ int            g_counts[NCODES];
__device__ float          g_loss;
__device__ int            g_valid;
__device__ int            g_idx[NTOK];
__device__ unsigned long long g_key[NTOK];
__device__ int            g_lcnt[NSEC];
__device__ unsigned short g_list[NSEC * NTOK];               /* 4 MB  */
__device__ uint32_t       g_eperm[NTILES * TILE_U32];        /* 2 MB  */
__device__ uint32_t       g_zperm[(NTOK / TQ) * TILE_U32];   /* 16 MB */

/* order-preserving float<->uint key */
__device__ __forceinline__ unsigned fkey(float f) {
    unsigned u = __float_as_uint(f);
    return (u & 0x80000000u) ? ~u : (u | 0x80000000u);
}
__device__ __forceinline__ float funkey(unsigned k) {
    return (k & 0x80000000u) ? __uint_as_float(k & 0x7fffffffu)
                             : __uint_as_float(~k);
}
__device__ __forceinline__ uint32_t smem_u32(const void* p) {
    uint32_t a;
    asm("{ .reg .u64 t; cvta.to.shared.u64 t, %1; cvt.u32.u64 %0, t; }" : "=r"(a) : "l"(p));
    return a;
}
#define CP_ASYNC16(dst, src) \
    asm volatile("cp.async.cg.shared.global [%0], [%1], 16;" :: "r"(dst), "l"(src) : "memory")
#define CP_COMMIT()  asm volatile("cp.async.commit_group;" ::: "memory")
#define CP_WAIT(n)   asm volatile("cp.async.wait_group %0;" :: "n"(n) : "memory")

#define MMA_BF16(c, av, bv)                                                     \
    asm volatile("mma.sync.aligned.m16n8k16.row.col.f32.bf16.bf16.f32 "         \
        "{%0,%1,%2,%3}, {%4,%5,%6,%7}, {%8,%9}, {%0,%1,%2,%3};"                 \
        : "+f"((c)[0]), "+f"((c)[1]), "+f"((c)[2]), "+f"((c)[3])                \
        : "r"((av).x), "r"((av).y), "r"((av).z), "r"((av).w),                   \
          "r"((bv).x), "r"((bv).y))

/* ------------------------------------------------------------------ */
__global__ void zero_kernel() {
    int i = blockIdx.x * 256 + threadIdx.x;
    if (i < NCODES) g_counts[i] = 0;
    if (i < NTOK)   g_key[i] = 0xFFFFFFFFFFFFFFFFull;
    if (i < NSEC)   g_lcnt[i] = 0;
    if (i == 0) { g_loss = 0.0f; g_valid = 0; }
}

/* ------------------------------------------------------------------ */
__global__ void enorm_kernel(const float* __restrict__ e) {
    int warp = (blockIdx.x * blockDim.x + threadIdx.x) >> 5;
    int lane = threadIdx.x & 31;
    if (warp >= NCODES) return;
    const float* row = e + (size_t)warp * CDIM;
    float s = 0.0f;
#pragma unroll
    for (int i = 0; i < CDIM / 32; i++) { float v = row[lane + 32 * i]; s += v * v; }
#pragma unroll
    for (int o = 16; o; o >>= 1) s += __shfl_down_sync(0xffffffffu, s, o);
    if (lane == 0) g_enorm[warp] = s;
}

/* ------------------------------------------------------------------ */
/* Pre-permute codebook/tokens to bf16 fragment layout.                */
__global__ void eperm_kernel(const float* __restrict__ e) {
    int v  = blockIdx.x * 256 + threadIdx.x;        /* NCODES*128 pairs */
    int ng = v >> 7, kp = v & 127;
    float2 ev = *(const float2*)(e + (size_t)ng * CDIM + 2 * kp);
    __nv_bfloat162 h = __floats2bfloat162_rn(ev.x, ev.y);
    int tile = ng >> 7, n = ng & 127;
    int s = kp >> 3, kk = (2 * kp) & 15;
    int nt = n >> 3, nc = n & 7;
    int lanep = nc * 4 + ((kk >> 1) & 3);
    int reg   = kk >> 3;
    g_eperm[tile * TILE_U32 + (nt * 16 + s) * 64 + ((lanep * 2) ^ ((s & 3) << 1)) + reg]
        = *(unsigned*)&h;
}

__global__ void zperm_kernel(const float* __restrict__ z) {
    int v  = blockIdx.x * 256 + threadIdx.x;        /* NTOK*128 pairs */
    int mg = v >> 7, kp = v & 127;
    float2 zv = *(const float2*)(z + (size_t)mg * CDIM + 2 * kp);
    __nv_bfloat162 h = __floats2bfloat162_rn(zv.x, zv.y);
    int blk = mg >> 7, m = mg & 127;
    int s = kp >> 3, kk = (2 * kp) & 15;
    int mt = m >> 4, lr = m & 15;
    int lanep = (lr & 7) * 4 + ((kk >> 1) & 3);
    int reg   = (lr >> 3) + 2 * (kk >> 3);
    g_zperm[blk * TILE_U32 + (mt * 16 + s) * 128 + ((lanep * 4) ^ ((s & 3) << 2)) + reg]
        = *(unsigned*)&h;
}

/* ------------------------------------------------------------------ */
/* Single-pass bf16 mma.sync over 32 tiles; per-(token, 64-code        */
/* sector) minima of et = e_norm - 2*dot_bf16 (each warp's epilogue    */
/* values span exactly one sector -> granularity is free). Sectors     */
/* with secMin <= rowMin + MARGIN go to per-sector token lists.        */
/* Margin proof (rounds 8-12): any code achieving the exact reference  */
/* argmin has et <= et_min + MARGIN, so its sector is flagged.         */
__global__ void __launch_bounds__(256, 1)
cand_kernel() {
    extern __shared__ char smem[];
    uint32_t* Asm    = (uint32_t*)(smem + SM_A);
    float*    Es     = (float*)(smem + SM_ES);
    unsigned* secMin = (unsigned*)(smem + SM_SMIN);   /* [64][128] sector-major */
    const uint32_t sbase = smem_u32(smem);

    const int tid    = threadIdx.x;
    const int lane   = tid & 31;
    const int wid    = tid >> 5;
    const int warp_m = wid >> 1;
    const int warp_n = wid & 1;
    const int g      = lane >> 2;
    const int tq     = lane & 3;

    for (int i = tid; i < TQ * NSEC; i += 256) secMin[i] = 0xFFFFFFFFu;

    /* A tile via cp.async (resident all tiles) */
    {
        const uint32_t* Ag = g_zperm + (size_t)blockIdx.x * TILE_U32;
#pragma unroll
        for (int i = 0; i < 16; i++) {
            int o = (i * 256 + tid) * 4;
            CP_ASYNC16(sbase + SM_A + o * 4, Ag + o);
        }
        CP_COMMIT();
    }
    /* B tile 0 */
    {
        const uint32_t* Bg = g_eperm;
#pragma unroll
        for (int i = 0; i < 16; i++) {
            int o = (i * 256 + tid) * 4;
            CP_ASYNC16(sbase + SM_B0 + o * 4, Bg + o);
        }
        CP_COMMIT();
    }

    int buf = 0;
#pragma unroll 1
    for (int tile = 0; tile < NTILES; tile++) {
        const int jt = tile * TNC;
        if (tile + 1 < NTILES) {
            const uint32_t* Bg = g_eperm + (size_t)(tile + 1) * TILE_U32;
            uint32_t dstb = sbase + (buf ? SM_B0 : SM_B1);
#pragma unroll
            for (int i = 0; i < 16; i++) {
                int o = (i * 256 + tid) * 4;
                CP_ASYNC16(dstb + o * 4, Bg + o);
            }
            CP_COMMIT();
            CP_WAIT(1);
        } else {
            CP_WAIT(0);
        }
        if (tid < TNC) Es[tid] = g_enorm[jt + tid];
        __syncthreads();

        const uint32_t* Bsm = (const uint32_t*)(smem + (buf ? SM_B1 : SM_B0));

        float acc[2][8][4];
#pragma unroll
        for (int mi = 0; mi < 2; mi++)
#pragma unroll
            for (int nj = 0; nj < 8; nj++)
#pragma unroll
                for (int r = 0; r < 4; r++) acc[mi][nj][r] = 0.0f;

#pragma unroll
        for (int s = 0; s < 16; s++) {
            uint4 a0 = *(const uint4*)(Asm + ((2 * warp_m + 0) * 16 + s) * 128 + ((lane * 4) ^ ((s & 3) << 2)));
            uint4 a1 = *(const uint4*)(Asm + ((2 * warp_m + 1) * 16 + s) * 128 + ((lane * 4) ^ ((s & 3) << 2)));
            uint2 bf[8];
#pragma unroll
            for (int nj = 0; nj < 8; nj++)
                bf[nj] = *(const uint2*)(Bsm + ((8 * warp_n + nj) * 16 + s) * 64 + ((lane * 2) ^ ((s & 3) << 1)));
#pragma unroll
            for (int nj = 0; nj < 8; nj++) {
                MMA_BF16(acc[0][nj], a0, bf[nj]);
                MMA_BF16(acc[1][nj], a1, bf[nj]);
            }
        }

        /* per-sector min: this warp's codes all lie in sector 2*tile+warp_n */
        float tmin[4] = {3.4e38f, 3.4e38f, 3.4e38f, 3.4e38f};
#pragma unroll
        for (int mi = 0; mi < 2; mi++)
#pragma unroll
            for (int nj = 0; nj < 8; nj++) {
                int colb = 64 * warp_n + 8 * nj + 2 * tq;
                float e0 = Es[colb], e1 = Es[colb + 1];
                tmin[2 * mi]     = fminf(tmin[2 * mi],     fmaf(-2.0f, acc[mi][nj][0], e0));
                tmin[2 * mi]     = fminf(tmin[2 * mi],     fmaf(-2.0f, acc[mi][nj][1], e1));
                tmin[2 * mi + 1] = fminf(tmin[2 * mi + 1], fmaf(-2.0f, acc[mi][nj][2], e0));
                tmin[2 * mi + 1] = fminf(tmin[2 * mi + 1], fmaf(-2.0f, acc[mi][nj][3], e1));
            }
        const int sec = 2 * tile + warp_n;
#pragma unroll
        for (int sl = 0; sl < 4; sl++) {
            float m_ = tmin[sl];
            m_ = fminf(m_, __shfl_xor_sync(0xffffffffu, m_, 1));
            m_ = fminf(m_, __shfl_xor_sync(0xffffffffu, m_, 2));
            if (tq == 0) {
                int row = 32 * warp_m + 16 * (sl >> 1) + 8 * (sl & 1) + g;
                atomicMin(secMin + sec * TQ + row, fkey(m_));
            }
        }
        __syncthreads();
        buf ^= 1;
    }

    /* flag sectors per token (key-space compares); append to lists */
    if (tid < TQ) {
        int row = tid;
        int tok = blockIdx.x * TQ + row;
        unsigned mk = 0xFFFFFFFFu;
#pragma unroll
        for (int s = 0; s < NSEC; s++)
            mk = min(mk, secMin[s * TQ + row]);
        unsigned thr_key = fkey(funkey(mk) + MARGIN);
#pragma unroll 1
        for (int s = 0; s < NSEC; s++) {
            if (secMin[s * TQ + row] <= thr_key) {
                int pos = atomicAdd(&g_lcnt[s], 1);
                g_list[s * NTOK + pos] = (unsigned short)tok;
            }
        }
    }
}

/* ------------------------------------------------------------------ */
/* Exact kernel: for each flagged (token, sector), compute reference-  */
/* exact d = fl(fl(Z - 2*dot) + e_norm) for the sector's 64 codes with */
/* sequential-k fp32 chains (round-4-validated ordering); resolve      */
/* global winner via atomicMin on (fkey(d)<<32)|idx (= reference min   */
/* + first-index tie rule). Covers ties: all tie-achievers flagged.    */
__global__ void __launch_bounds__(256, 1)
exact_kernel(const float* __restrict__ z, const float* __restrict__ e) {
    extern __shared__ char smem[];
    float* Esm  = (float*)(smem + EX_E);     /* [64][257] */
    float* ENsm = (float*)(smem + EX_EN);    /* [64]      */
    const int sec  = blockIdx.y;             /* 0..63 */
    const int spl  = blockIdx.x;             /* 0..EX_SPL-1 */
    const int tid  = threadIdx.x;
    const int lane = tid & 31;
    const int wid  = tid >> 5;
    float* zbuf = (float*)(smem + EX_Z) + wid * 260;
    const int cbase = sec * 64;              /* first global code of sector */

    /* stage sector codes fp32 into padded smem */
    {
        const float* eb = e + (size_t)cbase * CDIM;
        for (int i = tid; i < 64 * CDIM; i += 256) {
            int c = i >> 8, k = i & 255;
            Esm[c * EX_ESTRIDE + k] = eb[i];
        }
        if (tid < 64) ENsm[tid] = g_enorm[cbase + tid];
    }
    __syncthreads();

    const int L    = g_lcnt[sec];
    const int slot = spl * 8 + wid;          /* 0..15, stride 16 */

    for (int i = slot; i < L; i += EX_SPL * 8) {
        int tok = g_list[sec * NTOK + i];
        /* warp loads z row to its smem buffer */
        {
            const float4* zr = (const float4*)(z + (size_t)tok * CDIM);
            ((float4*)zbuf)[lane]      = zr[lane];
            ((float4*)zbuf)[lane + 32] = zr[lane + 32];
        }
        __syncwarp();

        /* 3 interleaved sequential fp32 chains: Z + 2 code dots       */
        /* lane l owns codes {l, l+32}: bank (l+k)%32 conflict-free    */
        float Zc = 0.0f, d0 = 0.0f, d1 = 0.0f;
        const float* e0p = Esm + (lane +  0) * EX_ESTRIDE;
        const float* e1p = Esm + (lane + 32) * EX_ESTRIDE;
#pragma unroll 8
        for (int k = 0; k < CDIM; k++) {
            float zv = zbuf[k];
            Zc = __fmaf_rn(zv, zv, Zc);
            d0 = __fmaf_rn(zv, e0p[k], d0);
            d1 = __fmaf_rn(zv, e1p[k], d1);
        }
        float v0 = __fadd_rn(__fmaf_rn(-2.0f, d0, Zc), ENsm[lane]);
        float v1 = __fadd_rn(__fmaf_rn(-2.0f, d1, Zc), ENsm[lane + 32]);

        unsigned long long key =       ((unsigned long long)fkey(v0) << 32) | (unsigned)(cbase + lane);
        key = min(key, ((unsigned long long)fkey(v1) << 32) | (unsigned)(cbase + lane + 32));
#pragma unroll
        for (int o = 16; o; o >>= 1) {
            unsigned long long ok = __shfl_xor_sync(0xffffffffu, key, o);
            key = min(key, ok);
        }
        if (lane == 0) atomicMin(&g_key[tok], key);
        __syncwarp();
    }
}

/* ------------------------------------------------------------------ */
/* Gather z_q/z_q_st + losses + histogram; also resolves idx from key. */
__global__ void gather_kernel(const float* __restrict__ z,
                              const int* __restrict__ mask,
                              const float* __restrict__ e,
                              float* __restrict__ out,
                              float* __restrict__ out_idx_f) {
    __shared__ float s_loss[8];
    __shared__ int   s_valid[8];
    int wid  = threadIdx.x >> 5;
    int lane = threadIdx.x & 31;
    int t    = blockIdx.x * 8 + wid;

    int mk  = mask[t];
    int idx = (int)(unsigned)(g_key[t] & 0xFFFFFFFFull);
    const float4* zr = (const float4*)(z + (size_t)t * CDIM);
    const float4* er = (const float4*)(e + (size_t)idx * CDIM);
    float4* o1 = (float4*)(out + (size_t)t * CDIM);
    float4* o2 = (float4*)(out + (size_t)NC_OUT + (size_t)t * CDIM);

    float ls = 0.0f;
#pragma unroll
    for (int i = 0; i < 2; i++) {
        int c = lane + 32 * i;
        float4 ev = er[c];
        float4 zv = zr[c];
        float4 q;
        if (mk) {
            q = ev;
            float dx = ev.x - zv.x, dy = ev.y - zv.y;
            float dz = ev.z - zv.z, dw = ev.w - zv.w;
            ls += dx * dx + dy * dy + dz * dz + dw * dw;
        } else {
            q = make_float4(0.0f, 0.0f, 0.0f, 0.0f);
        }
        o1[c] = q;
        o2[c] = q;
    }
#pragma unroll
    for (int o = 16; o; o >>= 1) ls += __shfl_down_sync(0xffffffffu, ls, o);
    if (lane == 0) {
        out_idx_f[t] = (float)idx;
        s_loss[wid]  = ls;
        s_valid[wid] = mk;
        if (mk) atomicAdd(&g_counts[idx], 1);
    }
    __syncthreads();
    if (threadIdx.x == 0) {
        float tot = 0.0f; int v = 0;
#pragma unroll
        for (int w = 0; w < 8; w++) { tot += s_loss[w]; v += s_valid[w]; }
        atomicAdd(&g_loss, tot);
        atomicAdd(&g_valid, v);
    }
}

/* ------------------------------------------------------------------ */
__global__ void finalize_kernel(float* __restrict__ out) {
    __shared__ float red[256];
    int tid = threadIdx.x;
    float nv    = (float)g_valid;
    float denom = nv + 1e-8f;
    float ent = 0.0f;
    for (int i = tid; i < NCODES; i += 256) {
        float p = (float)g_counts[i] / denom;
        ent += p * logf(p + 1e-8f);
    }
    red[tid] = ent;
    __syncthreads();
    for (int s = 128; s; s >>= 1) {
        if (tid < s) red[tid] += red[tid + s];
        __syncthreads();
    }
    if (tid == 0) {
        float valid = fmaxf(nv, 1.0f);
        float loss  = g_loss / valid;
        float* o = out + 2 * (size_t)NC_OUT + NTOK;
        o[0] = loss * 1.25f;
        o[1] = loss;
        o[2] = loss;
        o[3] = expf(-red[0]);
    }
}

/* ------------------------------------------------------------------ */
extern "C" void kernel_launch(void* const* d_in, const int* in_sizes, int n_in,
                              void* d_out, int out_size) {
    const float* z    = (const float*)d_in[0];
    const int*   mask = (const int*)d_in[1];
    const float* e    = (const float*)d_in[2];
    float*       out  = (float*)d_out;

    cudaFuncSetAttribute(cand_kernel,
                         cudaFuncAttributeMaxDynamicSharedMemorySize, SM_TOT);
    cudaFuncSetAttribute(exact_kernel,
                         cudaFuncAttributeMaxDynamicSharedMemorySize, EX_TOT);

    zero_kernel<<<NTOK / 256, 256>>>();
    enorm_kernel<<<NCODES / 8, 256>>>(e);
    eperm_kernel<<<NCODES * 128 / 256, 256>>>(e);
    zperm_kernel<<<NTOK * 128 / 256, 256>>>(z);
    cand_kernel<<<NTOK / TQ, 256, SM_TOT>>>();
    exact_kernel<<<dim3(EX_SPL, NSEC), 256, EX_TOT>>>(z, e);
    gather_kernel<<<NTOK / 8, 256>>>(z, mask, e, out, out + 2 * (size_t)NC_OUT);
    finalize_kernel<<<1, 256>>>(out);
}

// round 15
// speedup vs baseline: 6.0958x; 1.0096x over previous
#include <cuda_runtime.h>
#include <cuda_bf16.h>
#include <cstdint>
#include <math.h>

#define NCODES 4096
#define CDIM   256
#define NTOK   32768
#define NC_OUT (NTOK * CDIM)

#define TQ      128              /* tokens per CTA           */
#define TNC     128              /* codes per tile           */
#define NTILES  (NCODES / TNC)   /* 32                       */
#define NSEC    (NTILES * 2)     /* 64 sectors of 64 codes   */
#define MARGIN  4e-4f

#define TILE_U32 16384           /* 64 KB per permuted tile  */

/* cand smem layout (bytes): A 64K | B0 64K | B1 64K | Es | secMin */
#define SM_A      0
#define SM_B0     65536
#define SM_B1     131072
#define SM_ES     196608
#define SM_SMIN   197120         /* 64 x 128 u32 = 32 KB (sector-major) */
#define SM_TOT    229888         /* < 227 KiB cap */

/* exact-kernel smem: e sector (64 x 257 f32) | enorm | z bufs */
#define EX_ESTRIDE 257
#define EX_E      0
#define EX_EN     65792
#define EX_Z      66048          /* 8 warps x 260 floats */
#define EX_TOT    74368
#define EX_SPL    2              /* grid 2 x 64 = 128 CTAs */

__device__ float          g_enorm[NCODES];
__device__ int            g_counts[NCODES];
__device__ float          g_loss;
__device__ int            g_valid;
__device__ unsigned long long g_key[NTOK];
__device__ int            g_lcnt[NSEC];
__device__ unsigned short g_list[NSEC * NTOK];               /* 4 MB  */
__device__ uint32_t       g_eperm[NTILES * TILE_U32];        /* 2 MB  */

/* order-preserving float<->uint key */
__device__ __forceinline__ unsigned fkey(float f) {
    unsigned u = __float_as_uint(f);
    return (u & 0x80000000u) ? ~u : (u | 0x80000000u);
}
__device__ __forceinline__ float funkey(unsigned k) {
    return (k & 0x80000000u) ? __uint_as_float(k & 0x7fffffffu)
                             : __uint_as_float(~k);
}
__device__ __forceinline__ uint32_t smem_u32(const void* p) {
    uint32_t a;
    asm("{ .reg .u64 t; cvta.to.shared.u64 t, %1; cvt.u32.u64 %0, t; }" : "=r"(a) : "l"(p));
    return a;
}
#define CP_ASYNC16(dst, src) \
    asm volatile("cp.async.cg.shared.global [%0], [%1], 16;" :: "r"(dst), "l"(src) : "memory")
#define CP_COMMIT()  asm volatile("cp.async.commit_group;" ::: "memory")
#define CP_WAIT(n)   asm volatile("cp.async.wait_group %0;" :: "n"(n) : "memory")

#define MMA_BF16(c, av, bv)                                                     \
    asm volatile("mma.sync.aligned.m16n8k16.row.col.f32.bf16.bf16.f32 "         \
        "{%0,%1,%2,%3}, {%4,%5,%6,%7}, {%8,%9}, {%0,%1,%2,%3};"                 \
        : "+f"((c)[0]), "+f"((c)[1]), "+f"((c)[2]), "+f"((c)[3])                \
        : "r"((av).x), "r"((av).y), "r"((av).z), "r"((av).w),                   \
          "r"((bv).x), "r"((bv).y))

/* ------------------------------------------------------------------ */
__global__ void enorm_kernel(const float* __restrict__ e) {
    int warp = (blockIdx.x * blockDim.x + threadIdx.x) >> 5;
    int lane = threadIdx.x & 31;
    if (warp >= NCODES) return;
    const float* row = e + (size_t)warp * CDIM;
    float s = 0.0f;
#pragma unroll
    for (int i = 0; i < CDIM / 32; i++) { float v = row[lane + 32 * i]; s += v * v; }
#pragma unroll
    for (int o = 16; o; o >>= 1) s += __shfl_down_sync(0xffffffffu, s, o);
    if (lane == 0) g_enorm[warp] = s;
}

/* ------------------------------------------------------------------ */
/* Pre-permute codebook to bf16 fragment layout + all zero-init work.  */
__global__ void eperm_kernel(const float* __restrict__ e) {
    int v = blockIdx.x * 256 + threadIdx.x;         /* NCODES*128 pairs */
    /* fused init (grid 2048 blocks covers all ranges) */
    if (v < NCODES) g_counts[v] = 0;
    if (v < NTOK)   g_key[v] = 0xFFFFFFFFFFFFFFFFull;
    if (v < NSEC)   g_lcnt[v] = 0;
    if (v == 0) { g_loss = 0.0f; g_valid = 0; }

    int ng = v >> 7, kp = v & 127;
    float2 ev = *(const float2*)(e + (size_t)ng * CDIM + 2 * kp);
    __nv_bfloat162 h = __floats2bfloat162_rn(ev.x, ev.y);
    int tile = ng >> 7, n = ng & 127;
    int s = kp >> 3, kk = (2 * kp) & 15;
    int nt = n >> 3, nc = n & 7;
    int lanep = nc * 4 + ((kk >> 1) & 3);
    int reg   = kk >> 3;
    g_eperm[tile * TILE_U32 + (nt * 16 + s) * 64 + ((lanep * 2) ^ ((s & 3) << 1)) + reg]
        = *(unsigned*)&h;
}

/* ------------------------------------------------------------------ */
/* Single-pass bf16 mma.sync over 32 tiles; per-(token, 64-code        */
/* sector) minima of et = e_norm - 2*dot_bf16. A tile converted        */
/* inline f32->bf16 with the same intrinsic/layout as the old zperm    */
/* (bit-identical fragments). Sectors with secMin <= rowMin + MARGIN   */
/* go to per-sector token lists. Margin proof (rounds 8-14): any code  */
/* achieving the exact reference argmin has et <= et_min + MARGIN.     */
__global__ void __launch_bounds__(256, 1)
cand_kernel(const float* __restrict__ z) {
    extern __shared__ char smem[];
    uint32_t* Asm    = (uint32_t*)(smem + SM_A);
    float*    Es     = (float*)(smem + SM_ES);
    unsigned* secMin = (unsigned*)(smem + SM_SMIN);   /* [64][128] sector-major */
    const uint32_t sbase = smem_u32(smem);

    const int tid    = threadIdx.x;
    const int lane   = tid & 31;
    const int wid    = tid >> 5;
    const int warp_m = wid >> 1;
    const int warp_n = wid & 1;
    const int g      = lane >> 2;
    const int tq     = lane & 3;

    for (int i = tid; i < TQ * NSEC; i += 256) secMin[i] = 0xFFFFFFFFu;

    /* B tile 0 via cp.async first (overlaps A conversion below) */
    {
        const uint32_t* Bg = g_eperm;
#pragma unroll
        for (int i = 0; i < 16; i++) {
            int o = (i * 256 + tid) * 4;
            CP_ASYNC16(sbase + SM_B0 + o * 4, Bg + o);
        }
        CP_COMMIT();
    }

    /* A: inline f32 -> bf16 fragment-permuted smem (once per CTA) */
    {
        const float2* zg = (const float2*)(z + (size_t)blockIdx.x * TQ * CDIM);
#pragma unroll 8
        for (int it = 0; it < 64; it++) {
            int v = it * 256 + tid;
            int m = v >> 7, kp = v & 127;
            float2 zv = zg[(size_t)m * 128 + kp];
            __nv_bfloat162 h = __floats2bfloat162_rn(zv.x, zv.y);
            int s  = kp >> 3;
            int kk = (2 * kp) & 15;
            int mt = m >> 4, lr = m & 15;
            int lanep = (lr & 7) * 4 + ((kk >> 1) & 3);
            int reg   = (lr >> 3) + 2 * (kk >> 3);
            Asm[(mt * 16 + s) * 128 + ((lanep * 4) ^ ((s & 3) << 2)) + reg]
                = *(unsigned*)&h;
        }
    }

    int buf = 0;
#pragma unroll 1
    for (int tile = 0; tile < NTILES; tile++) {
        const int jt = tile * TNC;
        if (tile + 1 < NTILES) {
            const uint32_t* Bg = g_eperm + (size_t)(tile + 1) * TILE_U32;
            uint32_t dstb = sbase + (buf ? SM_B0 : SM_B1);
#pragma unroll
            for (int i = 0; i < 16; i++) {
                int o = (i * 256 + tid) * 4;
                CP_ASYNC16(dstb + o * 4, Bg + o);
            }
            CP_COMMIT();
            CP_WAIT(1);
        } else {
            CP_WAIT(0);
        }
        if (tid < TNC) Es[tid] = g_enorm[jt + tid];
        __syncthreads();          /* also publishes Asm stores (tile 0) */

        const uint32_t* Bsm = (const uint32_t*)(smem + (buf ? SM_B1 : SM_B0));

        float acc[2][8][4];
#pragma unroll
        for (int mi = 0; mi < 2; mi++)
#pragma unroll
            for (int nj = 0; nj < 8; nj++)
#pragma unroll
                for (int r = 0; r < 4; r++) acc[mi][nj][r] = 0.0f;

#pragma unroll
        for (int s = 0; s < 16; s++) {
            uint4 a0 = *(const uint4*)(Asm + ((2 * warp_m + 0) * 16 + s) * 128 + ((lane * 4) ^ ((s & 3) << 2)));
            uint4 a1 = *(const uint4*)(Asm + ((2 * warp_m + 1) * 16 + s) * 128 + ((lane * 4) ^ ((s & 3) << 2)));
            uint2 bf[8];
#pragma unroll
            for (int nj = 0; nj < 8; nj++)
                bf[nj] = *(const uint2*)(Bsm + ((8 * warp_n + nj) * 16 + s) * 64 + ((lane * 2) ^ ((s & 3) << 1)));
#pragma unroll
            for (int nj = 0; nj < 8; nj++) {
                MMA_BF16(acc[0][nj], a0, bf[nj]);
                MMA_BF16(acc[1][nj], a1, bf[nj]);
            }
        }

        /* per-sector min: this warp's codes all lie in sector 2*tile+warp_n */
        float tmin[4] = {3.4e38f, 3.4e38f, 3.4e38f, 3.4e38f};
#pragma unroll
        for (int mi = 0; mi < 2; mi++)
#pragma unroll
            for (int nj = 0; nj < 8; nj++) {
                int colb = 64 * warp_n + 8 * nj + 2 * tq;
                float e0 = Es[colb], e1 = Es[colb + 1];
                tmin[2 * mi]     = fminf(tmin[2 * mi],     fmaf(-2.0f, acc[mi][nj][0], e0));
                tmin[2 * mi]     = fminf(tmin[2 * mi],     fmaf(-2.0f, acc[mi][nj][1], e1));
                tmin[2 * mi + 1] = fminf(tmin[2 * mi + 1], fmaf(-2.0f, acc[mi][nj][2], e0));
                tmin[2 * mi + 1] = fminf(tmin[2 * mi + 1], fmaf(-2.0f, acc[mi][nj][3], e1));
            }
        const int sec = 2 * tile + warp_n;
#pragma unroll
        for (int sl = 0; sl < 4; sl++) {
            float m_ = tmin[sl];
            m_ = fminf(m_, __shfl_xor_sync(0xffffffffu, m_, 1));
            m_ = fminf(m_, __shfl_xor_sync(0xffffffffu, m_, 2));
            if (tq == 0) {
                int row = 32 * warp_m + 16 * (sl >> 1) + 8 * (sl & 1) + g;
                atomicMin(secMin + sec * TQ + row, fkey(m_));
            }
        }
        __syncthreads();
        buf ^= 1;
    }

    /* flag sectors per token (key-space compares); append to lists */
    if (tid < TQ) {
        int row = tid;
        int tok = blockIdx.x * TQ + row;
        unsigned mk = 0xFFFFFFFFu;
#pragma unroll
        for (int s = 0; s < NSEC; s++)
            mk = min(mk, secMin[s * TQ + row]);
        unsigned thr_key = fkey(funkey(mk) + MARGIN);
#pragma unroll 1
        for (int s = 0; s < NSEC; s++) {
            if (secMin[s * TQ + row] <= thr_key) {
                int pos = atomicAdd(&g_lcnt[s], 1);
                g_list[s * NTOK + pos] = (unsigned short)tok;
            }
        }
    }
}

/* ------------------------------------------------------------------ */
/* Exact kernel: for each flagged (token, sector), compute reference-  */
/* exact d = fl(fl(Z - 2*dot) + e_norm) for the sector's 64 codes with */
/* sequential-k fp32 chains (round-4-validated ordering); resolve      */
/* global winner via atomicMin on (fkey(d)<<32)|idx (= reference min   */
/* + first-index tie rule). Covers ties: all tie-achievers flagged.    */
__global__ void __launch_bounds__(256, 1)
exact_kernel(const float* __restrict__ z, const float* __restrict__ e) {
    extern __shared__ char smem[];
    float* Esm  = (float*)(smem + EX_E);     /* [64][257] */
    float* ENsm = (float*)(smem + EX_EN);    /* [64]      */
    const int sec  = blockIdx.y;             /* 0..63 */
    const int spl  = blockIdx.x;             /* 0..EX_SPL-1 */
    const int tid  = threadIdx.x;
    const int lane = tid & 31;
    const int wid  = tid >> 5;
    float* zbuf = (float*)(smem + EX_Z) + wid * 260;
    const int cbase = sec * 64;              /* first global code of sector */

    /* stage sector codes fp32 into padded smem */
    {
        const float* eb = e + (size_t)cbase * CDIM;
        for (int i = tid; i < 64 * CDIM; i += 256) {
            int c = i >> 8, k = i & 255;
            Esm[c * EX_ESTRIDE + k] = eb[i];
        }
        if (tid < 64) ENsm[tid] = g_enorm[cbase + tid];
    }
    __syncthreads();

    const int L    = g_lcnt[sec];
    const int slot = spl * 8 + wid;          /* 0..15, stride 16 */

    for (int i = slot; i < L; i += EX_SPL * 8) {
        int tok = g_list[sec * NTOK + i];
        /* warp loads z row to its smem buffer */
        {
            const float4* zr = (const float4*)(z + (size_t)tok * CDIM);
            ((float4*)zbuf)[lane]      = zr[lane];
            ((float4*)zbuf)[lane + 32] = zr[lane + 32];
        }
        __syncwarp();

        /* 3 interleaved sequential fp32 chains: Z + 2 code dots       */
        /* lane l owns codes {l, l+32}: bank (l+k)%32 conflict-free    */
        float Zc = 0.0f, d0 = 0.0f, d1 = 0.0f;
        const float* e0p = Esm + (lane +  0) * EX_ESTRIDE;
        const float* e1p = Esm + (lane + 32) * EX_ESTRIDE;
#pragma unroll 8
        for (int k = 0; k < CDIM; k++) {
            float zv = zbuf[k];
            Zc = __fmaf_rn(zv, zv, Zc);
            d0 = __fmaf_rn(zv, e0p[k], d0);
            d1 = __fmaf_rn(zv, e1p[k], d1);
        }
        float v0 = __fadd_rn(__fmaf_rn(-2.0f, d0, Zc), ENsm[lane]);
        float v1 = __fadd_rn(__fmaf_rn(-2.0f, d1, Zc), ENsm[lane + 32]);

        unsigned long long key =       ((unsigned long long)fkey(v0) << 32) | (unsigned)(cbase + lane);
        key = min(key, ((unsigned long long)fkey(v1) << 32) | (unsigned)(cbase + lane + 32));
#pragma unroll
        for (int o = 16; o; o >>= 1) {
            unsigned long long ok = __shfl_xor_sync(0xffffffffu, key, o);
            key = min(key, ok);
        }
        if (lane == 0) atomicMin(&g_key[tok], key);
        __syncwarp();
    }
}

/* ------------------------------------------------------------------ */
/* Gather z_q/z_q_st + losses + histogram; resolves idx from key.      */
__global__ void gather_kernel(const float* __restrict__ z,
                              const int* __restrict__ mask,
                              const float* __restrict__ e,
                              float* __restrict__ out,
                              float* __restrict__ out_idx_f) {
    __shared__ float s_loss[8];
    __shared__ int   s_valid[8];
    int wid  = threadIdx.x >> 5;
    int lane = threadIdx.x & 31;
    int t    = blockIdx.x * 8 + wid;

    int mk  = mask[t];
    int idx = (int)(unsigned)(g_key[t] & 0xFFFFFFFFull);
    const float4* zr = (const float4*)(z + (size_t)t * CDIM);
    const float4* er = (const float4*)(e + (size_t)idx * CDIM);
    float4* o1 = (float4*)(out + (size_t)t * CDIM);
    float4* o2 = (float4*)(out + (size_t)NC_OUT + (size_t)t * CDIM);

    float ls = 0.0f;
#pragma unroll
    for (int i = 0; i < 2; i++) {
        int c = lane + 32 * i;
        float4 ev = er[c];
        float4 zv = zr[c];
        float4 q;
        if (mk) {
            q = ev;
            float dx = ev.x - zv.x, dy = ev.y - zv.y;
            float dz = ev.z - zv.z, dw = ev.w - zv.w;
            ls += dx * dx + dy * dy + dz * dz + dw * dw;
        } else {
            q = make_float4(0.0f, 0.0f, 0.0f, 0.0f);
        }
        o1[c] = q;
        o2[c] = q;
    }
#pragma unroll
    for (int o = 16; o; o >>= 1) ls += __shfl_down_sync(0xffffffffu, ls, o);
    if (lane == 0) {
        out_idx_f[t] = (float)idx;
        s_loss[wid]  = ls;
        s_valid[wid] = mk;
        if (mk) atomicAdd(&g_counts[idx], 1);
    }
    __syncthreads();
    if (threadIdx.x == 0) {
        float tot = 0.0f; int v = 0;
#pragma unroll
        for (int w = 0; w < 8; w++) { tot += s_loss[w]; v += s_valid[w]; }
        atomicAdd(&g_loss, tot);
        atomicAdd(&g_valid, v);
    }
}

/* ------------------------------------------------------------------ */
__global__ void finalize_kernel(float* __restrict__ out) {
    __shared__ float red[256];
    int tid = threadIdx.x;
    float nv    = (float)g_valid;
    float denom = nv + 1e-8f;
    float ent = 0.0f;
    for (int i = tid; i < NCODES; i += 256) {
        float p = (float)g_counts[i] / denom;
        ent += p * logf(p + 1e-8f);
    }
    red[tid] = ent;
    __syncthreads();
    for (int s = 128; s; s >>= 1) {
        if (tid < s) red[tid] += red[tid + s];
        __syncthreads();
    }
    if (tid == 0) {
        float valid = fmaxf(nv, 1.0f);
        float loss  = g_loss / valid;
        float* o = out + 2 * (size_t)NC_OUT + NTOK;
        o[0] = loss * 1.25f;
        o[1] = loss;
        o[2] = loss;
        o[3] = expf(-red[0]);
    }
}

/* ------------------------------------------------------------------ */
extern "C" void kernel_launch(void* const* d_in, const int* in_sizes, int n_in,
                              void* d_out, int out_size) {
    const float* z    = (const float*)d_in[0];
    const int*   mask = (const int*)d_in[1];
    const float* e    = (const float*)d_in[2];
    float*       out  = (float*)d_out;

    cudaFuncSetAttribute(cand_kernel,
                         cudaFuncAttributeMaxDynamicSharedMemorySize, SM_TOT);
    cudaFuncSetAttribute(exact_kernel,
                         cudaFuncAttributeMaxDynamicSharedMemorySize, EX_TOT);

    eperm_kernel<<<NCODES * 128 / 256, 256>>>(e);   /* + fused zero-init */
    enorm_kernel<<<NCODES / 8, 256>>>(e);
    cand_kernel<<<NTOK / TQ, 256, SM_TOT>>>(z);
    exact_kernel<<<dim3(EX_SPL, NSEC), 256, EX_TOT>>>(z, e);
    gather_kernel<<<NTOK / 8, 256>>>(z, mask, e, out, out + 2 * (size_t)NC_OUT);
    finalize_kernel<<<1, 256>>>(out);
}

// round 16
// speedup vs baseline: 6.4713x; 1.0616x over previous
#include <cuda_runtime.h>
#include <cuda_bf16.h>
#include <cstdint>
#include <math.h>

#define NCODES 4096
#define CDIM   256
#define NTOK   32768
#define NC_OUT (NTOK * CDIM)

#define TQ      128              /* tokens per CTA           */
#define TNC     128              /* codes per tile           */
#define NTILES  (NCODES / TNC)   /* 32                       */
#define NSEC    (NTILES * 2)     /* 64 sectors of 64 codes   */
#define MARGIN  4e-4f

#define TILE_U32 16384           /* 64 KB per permuted tile  */

/* cand smem layout (bytes): A 64K | B0 64K | B1 64K | Es | secMin */
#define SM_A      0
#define SM_B0     65536
#define SM_B1     131072
#define SM_ES     196608
#define SM_SMIN   197120         /* 64 x 128 u32 = 32 KB (sector-major) */
#define SM_TOT    229888         /* < 227 KiB cap */

/* exact-kernel smem: e sector (64 x 257 f32) | enorm | z bufs */
#define EX_ESTRIDE 257
#define EX_E      0
#define EX_EN     65792
#define EX_Z      66048          /* 8 warps x 260 floats */
#define EX_TOT    74368          /* 3 CTAs/SM: 3 x 74368 = 218 KiB */
#define EX_SPL    8              /* grid 8 x 64 = 512 CTAs */

__device__ float          g_enorm[NCODES];
__device__ int            g_counts[NCODES];
__device__ float          g_loss;
__device__ int            g_valid;
__device__ unsigned long long g_key[NTOK];
__device__ int            g_lcnt[NSEC];
__device__ unsigned short g_list[NSEC * NTOK];               /* 4 MB  */
__device__ uint32_t       g_eperm[NTILES * TILE_U32];        /* 2 MB  */

/* order-preserving float<->uint key */
__device__ __forceinline__ unsigned fkey(float f) {
    unsigned u = __float_as_uint(f);
    return (u & 0x80000000u) ? ~u : (u | 0x80000000u);
}
__device__ __forceinline__ float funkey(unsigned k) {
    return (k & 0x80000000u) ? __uint_as_float(k & 0x7fffffffu)
                             : __uint_as_float(~k);
}
__device__ __forceinline__ uint32_t smem_u32(const void* p) {
    uint32_t a;
    asm("{ .reg .u64 t; cvta.to.shared.u64 t, %1; cvt.u32.u64 %0, t; }" : "=r"(a) : "l"(p));
    return a;
}
#define CP_ASYNC16(dst, src) \
    asm volatile("cp.async.cg.shared.global [%0], [%1], 16;" :: "r"(dst), "l"(src) : "memory")
#define CP_COMMIT()  asm volatile("cp.async.commit_group;" ::: "memory")
#define CP_WAIT(n)   asm volatile("cp.async.wait_group %0;" :: "n"(n) : "memory")

#define MMA_BF16(c, av, bv)                                                     \
    asm volatile("mma.sync.aligned.m16n8k16.row.col.f32.bf16.bf16.f32 "         \
        "{%0,%1,%2,%3}, {%4,%5,%6,%7}, {%8,%9}, {%0,%1,%2,%3};"                 \
        : "+f"((c)[0]), "+f"((c)[1]), "+f"((c)[2]), "+f"((c)[3])                \
        : "r"((av).x), "r"((av).y), "r"((av).z), "r"((av).w),                   \
          "r"((bv).x), "r"((bv).y))

/* ------------------------------------------------------------------ */
__global__ void enorm_kernel(const float* __restrict__ e) {
    int warp = (blockIdx.x * blockDim.x + threadIdx.x) >> 5;
    int lane = threadIdx.x & 31;
    if (warp >= NCODES) return;
    const float* row = e + (size_t)warp * CDIM;
    float s = 0.0f;
#pragma unroll
    for (int i = 0; i < CDIM / 32; i++) { float v = row[lane + 32 * i]; s += v * v; }
#pragma unroll
    for (int o = 16; o; o >>= 1) s += __shfl_down_sync(0xffffffffu, s, o);
    if (lane == 0) g_enorm[warp] = s;
}

/* ------------------------------------------------------------------ */
/* Pre-permute codebook to bf16 fragment layout + all zero-init work.  */
__global__ void eperm_kernel(const float* __restrict__ e) {
    int v = blockIdx.x * 256 + threadIdx.x;         /* NCODES*128 pairs */
    if (v < NCODES) g_counts[v] = 0;
    if (v < NTOK)   g_key[v] = 0xFFFFFFFFFFFFFFFFull;
    if (v < NSEC)   g_lcnt[v] = 0;
    if (v == 0) { g_loss = 0.0f; g_valid = 0; }

    int ng = v >> 7, kp = v & 127;
    float2 ev = *(const float2*)(e + (size_t)ng * CDIM + 2 * kp);
    __nv_bfloat162 h = __floats2bfloat162_rn(ev.x, ev.y);
    int tile = ng >> 7, n = ng & 127;
    int s = kp >> 3, kk = (2 * kp) & 15;
    int nt = n >> 3, nc = n & 7;
    int lanep = nc * 4 + ((kk >> 1) & 3);
    int reg   = kk >> 3;
    g_eperm[tile * TILE_U32 + (nt * 16 + s) * 64 + ((lanep * 2) ^ ((s & 3) << 1)) + reg]
        = *(unsigned*)&h;
}

/* ------------------------------------------------------------------ */
/* Single-pass bf16 mma.sync over 32 tiles; per-(token, 64-code        */
/* sector) minima of et = e_norm - 2*dot_bf16. Sectors with            */
/* secMin <= rowMin + MARGIN go to per-sector token lists. Margin      */
/* proof (rounds 8-14): any code achieving the exact reference argmin  */
/* has et <= et_min + MARGIN, so its sector is flagged.                */
__global__ void __launch_bounds__(256, 1)
cand_kernel(const float* __restrict__ z) {
    extern __shared__ char smem[];
    uint32_t* Asm    = (uint32_t*)(smem + SM_A);
    float*    Es     = (float*)(smem + SM_ES);
    unsigned* secMin = (unsigned*)(smem + SM_SMIN);   /* [64][128] sector-major */
    const uint32_t sbase = smem_u32(smem);

    const int tid    = threadIdx.x;
    const int lane   = tid & 31;
    const int wid    = tid >> 5;
    const int warp_m = wid >> 1;
    const int warp_n = wid & 1;
    const int g      = lane >> 2;
    const int tq     = lane & 3;

    for (int i = tid; i < TQ * NSEC; i += 256) secMin[i] = 0xFFFFFFFFu;

    /* B tile 0 via cp.async first (overlaps A conversion below) */
    {
        const uint32_t* Bg = g_eperm;
#pragma unroll
        for (int i = 0; i < 16; i++) {
            int o = (i * 256 + tid) * 4;
            CP_ASYNC16(sbase + SM_B0 + o * 4, Bg + o);
        }
        CP_COMMIT();
    }

    /* A: inline f32 -> bf16 fragment-permuted smem (once per CTA) */
    {
        const float2* zg = (const float2*)(z + (size_t)blockIdx.x * TQ * CDIM);
#pragma unroll 8
        for (int it = 0; it < 64; it++) {
            int v = it * 256 + tid;
            int m = v >> 7, kp = v & 127;
            float2 zv = zg[(size_t)m * 128 + kp];
            __nv_bfloat162 h = __floats2bfloat162_rn(zv.x, zv.y);
            int s  = kp >> 3;
            int kk = (2 * kp) & 15;
            int mt = m >> 4, lr = m & 15;
            int lanep = (lr & 7) * 4 + ((kk >> 1) & 3);
            int reg   = (lr >> 3) + 2 * (kk >> 3);
            Asm[(mt * 16 + s) * 128 + ((lanep * 4) ^ ((s & 3) << 2)) + reg]
                = *(unsigned*)&h;
        }
    }

    int buf = 0;
#pragma unroll 1
    for (int tile = 0; tile < NTILES; tile++) {
        const int jt = tile * TNC;
        if (tile + 1 < NTILES) {
            const uint32_t* Bg = g_eperm + (size_t)(tile + 1) * TILE_U32;
            uint32_t dstb = sbase + (buf ? SM_B0 : SM_B1);
#pragma unroll
            for (int i = 0; i < 16; i++) {
                int o = (i * 256 + tid) * 4;
                CP_ASYNC16(dstb + o * 4, Bg + o);
            }
            CP_COMMIT();
            CP_WAIT(1);
        } else {
            CP_WAIT(0);
        }
        if (tid < TNC) Es[tid] = g_enorm[jt + tid];
        __syncthreads();          /* also publishes Asm stores (tile 0) */

        const uint32_t* Bsm = (const uint32_t*)(smem + (buf ? SM_B1 : SM_B0));

        float acc[2][8][4];
#pragma unroll
        for (int mi = 0; mi < 2; mi++)
#pragma unroll
            for (int nj = 0; nj < 8; nj++)
#pragma unroll
                for (int r = 0; r < 4; r++) acc[mi][nj][r] = 0.0f;

#pragma unroll
        for (int s = 0; s < 16; s++) {
            uint4 a0 = *(const uint4*)(Asm + ((2 * warp_m + 0) * 16 + s) * 128 + ((lane * 4) ^ ((s & 3) << 2)));
            uint4 a1 = *(const uint4*)(Asm + ((2 * warp_m + 1) * 16 + s) * 128 + ((lane * 4) ^ ((s & 3) << 2)));
            uint2 bf[8];
#pragma unroll
            for (int nj = 0; nj < 8; nj++)
                bf[nj] = *(const uint2*)(Bsm + ((8 * warp_n + nj) * 16 + s) * 64 + ((lane * 2) ^ ((s & 3) << 1)));
#pragma unroll
            for (int nj = 0; nj < 8; nj++) {
                MMA_BF16(acc[0][nj], a0, bf[nj]);
                MMA_BF16(acc[1][nj], a1, bf[nj]);
            }
        }

        /* per-sector min: this warp's codes all lie in sector 2*tile+warp_n */
        float tmin[4] = {3.4e38f, 3.4e38f, 3.4e38f, 3.4e38f};
#pragma unroll
        for (int mi = 0; mi < 2; mi++)
#pragma unroll
            for (int nj = 0; nj < 8; nj++) {
                int colb = 64 * warp_n + 8 * nj + 2 * tq;
                float e0 = Es[colb], e1 = Es[colb + 1];
                tmin[2 * mi]     = fminf(tmin[2 * mi],     fmaf(-2.0f, acc[mi][nj][0], e0));
                tmin[2 * mi]     = fminf(tmin[2 * mi],     fmaf(-2.0f, acc[mi][nj][1], e1));
                tmin[2 * mi + 1] = fminf(tmin[2 * mi + 1], fmaf(-2.0f, acc[mi][nj][2], e0));
                tmin[2 * mi + 1] = fminf(tmin[2 * mi + 1], fmaf(-2.0f, acc[mi][nj][3], e1));
            }
        const int sec = 2 * tile + warp_n;
#pragma unroll
        for (int sl = 0; sl < 4; sl++) {
            float m_ = tmin[sl];
            m_ = fminf(m_, __shfl_xor_sync(0xffffffffu, m_, 1));
            m_ = fminf(m_, __shfl_xor_sync(0xffffffffu, m_, 2));
            if (tq == 0) {
                int row = 32 * warp_m + 16 * (sl >> 1) + 8 * (sl & 1) + g;
                atomicMin(secMin + sec * TQ + row, fkey(m_));
            }
        }
        __syncthreads();
        buf ^= 1;
    }

    /* flag sectors per token (key-space compares); append to lists */
    if (tid < TQ) {
        int row = tid;
        int tok = blockIdx.x * TQ + row;
        unsigned mk = 0xFFFFFFFFu;
#pragma unroll
        for (int s = 0; s < NSEC; s++)
            mk = min(mk, secMin[s * TQ + row]);
        unsigned thr_key = fkey(funkey(mk) + MARGIN);
#pragma unroll 1
        for (int s = 0; s < NSEC; s++) {
            if (secMin[s * TQ + row] <= thr_key) {
                int pos = atomicAdd(&g_lcnt[s], 1);
                g_list[s * NTOK + pos] = (unsigned short)tok;
            }
        }
    }
}

/* ------------------------------------------------------------------ */
/* Exact kernel: for each flagged (token, sector), compute reference-  */
/* exact d = fl(fl(Z - 2*dot) + e_norm) for the sector's 64 codes with */
/* sequential-k fp32 chains (round-4-validated ordering); resolve      */
/* global winner via atomicMin on (fkey(d)<<32)|idx (= reference min   */
/* + first-index tie rule). EX_SPL=8 -> 512 CTAs, 3 CTAs/SM for        */
/* latency hiding + load balancing (round-15 occupancy fix).           */
__global__ void __launch_bounds__(256, 3)
exact_kernel(const float* __restrict__ z, const float* __restrict__ e) {
    extern __shared__ char smem[];
    float* Esm  = (float*)(smem + EX_E);     /* [64][257] */
    float* ENsm = (float*)(smem + EX_EN);    /* [64]      */
    const int sec  = blockIdx.y;             /* 0..63 */
    const int spl  = blockIdx.x;             /* 0..EX_SPL-1 */
    const int tid  = threadIdx.x;
    const int lane = tid & 31;
    const int wid  = tid >> 5;
    float* zbuf = (float*)(smem + EX_Z) + wid * 260;
    const int cbase = sec * 64;              /* first global code of sector */

    /* stage sector codes fp32 into padded smem */
    {
        const float* eb = e + (size_t)cbase * CDIM;
        for (int i = tid; i < 64 * CDIM; i += 256) {
            int c = i >> 8, k = i & 255;
            Esm[c * EX_ESTRIDE + k] = eb[i];
        }
        if (tid < 64) ENsm[tid] = g_enorm[cbase + tid];
    }
    __syncthreads();

    const int L    = g_lcnt[sec];
    const int slot = spl * 8 + wid;          /* 0..63, stride 64 */

    for (int i = slot; i < L; i += EX_SPL * 8) {
        int tok = g_list[sec * NTOK + i];
        /* warp loads z row to its smem buffer */
        {
            const float4* zr = (const float4*)(z + (size_t)tok * CDIM);
            ((float4*)zbuf)[lane]      = zr[lane];
            ((float4*)zbuf)[lane + 32] = zr[lane + 32];
        }
        __syncwarp();

        /* 3 interleaved sequential fp32 chains: Z + 2 code dots       */
        /* lane l owns codes {l, l+32}: bank (l+k)%32 conflict-free    */
        float Zc = 0.0f, d0 = 0.0f, d1 = 0.0f;
        const float* e0p = Esm + (lane +  0) * EX_ESTRIDE;
        const float* e1p = Esm + (lane + 32) * EX_ESTRIDE;
#pragma unroll 8
        for (int k = 0; k < CDIM; k++) {
            float zv = zbuf[k];
            Zc = __fmaf_rn(zv, zv, Zc);
            d0 = __fmaf_rn(zv, e0p[k], d0);
            d1 = __fmaf_rn(zv, e1p[k], d1);
        }
        float v0 = __fadd_rn(__fmaf_rn(-2.0f, d0, Zc), ENsm[lane]);
        float v1 = __fadd_rn(__fmaf_rn(-2.0f, d1, Zc), ENsm[lane + 32]);

        unsigned long long key =       ((unsigned long long)fkey(v0) << 32) | (unsigned)(cbase + lane);
        key = min(key, ((unsigned long long)fkey(v1) << 32) | (unsigned)(cbase + lane + 32));
#pragma unroll
        for (int o = 16; o; o >>= 1) {
            unsigned long long ok = __shfl_xor_sync(0xffffffffu, key, o);
            key = min(key, ok);
        }
        if (lane == 0) atomicMin(&g_key[tok], key);
        __syncwarp();
    }
}

/* ------------------------------------------------------------------ */
/* Gather z_q/z_q_st + losses + histogram; resolves idx from key.      */
__global__ void gather_kernel(const float* __restrict__ z,
                              const int* __restrict__ mask,
                              const float* __restrict__ e,
                              float* __restrict__ out,
                              float* __restrict__ out_idx_f) {
    __shared__ float s_loss[8];
    __shared__ int   s_valid[8];
    int wid  = threadIdx.x >> 5;
    int lane = threadIdx.x & 31;
    int t    = blockIdx.x * 8 + wid;

    int mk  = mask[t];
    int idx = (int)(unsigned)(g_key[t] & 0xFFFFFFFFull);
    const float4* zr = (const float4*)(z + (size_t)t * CDIM);
    const float4* er = (const float4*)(e + (size_t)idx * CDIM);
    float4* o1 = (float4*)(out + (size_t)t * CDIM);
    float4* o2 = (float4*)(out + (size_t)NC_OUT + (size_t)t * CDIM);

    float ls = 0.0f;
#pragma unroll
    for (int i = 0; i < 2; i++) {
        int c = lane + 32 * i;
        float4 ev = er[c];
        float4 zv = zr[c];
        float4 q;
        if (mk) {
            q = ev;
            float dx = ev.x - zv.x, dy = ev.y - zv.y;
            float dz = ev.z - zv.z, dw = ev.w - zv.w;
            ls += dx * dx + dy * dy + dz * dz + dw * dw;
        } else {
            q = make_float4(0.0f, 0.0f, 0.0f, 0.0f);
        }
        o1[c] = q;
        o2[c] = q;
    }
#pragma unroll
    for (int o = 16; o; o >>= 1) ls += __shfl_down_sync(0xffffffffu, ls, o);
    if (lane == 0) {
        out_idx_f[t] = (float)idx;
        s_loss[wid]  = ls;
        s_valid[wid] = mk;
        if (mk) atomicAdd(&g_counts[idx], 1);
    }
    __syncthreads();
    if (threadIdx.x == 0) {
        float tot = 0.0f; int v = 0;
#pragma unroll
        for (int w = 0; w < 8; w++) { tot += s_loss[w]; v += s_valid[w]; }
        atomicAdd(&g_loss, tot);
        atomicAdd(&g_valid, v);
    }
}

/* ------------------------------------------------------------------ */
__global__ void finalize_kernel(float* __restrict__ out) {
    __shared__ float red[256];
    int tid = threadIdx.x;
    float nv    = (float)g_valid;
    float denom = nv + 1e-8f;
    float ent = 0.0f;
    for (int i = tid; i < NCODES; i += 256) {
        float p = (float)g_counts[i] / denom;
        ent += p * logf(p + 1e-8f);
    }
    red[tid] = ent;
    __syncthreads();
    for (int s = 128; s; s >>= 1) {
        if (tid < s) red[tid] += red[tid + s];
        __syncthreads();
    }
    if (tid == 0) {
        float valid = fmaxf(nv, 1.0f);
        float loss  = g_loss / valid;
        float* o = out + 2 * (size_t)NC_OUT + NTOK;
        o[0] = loss * 1.25f;
        o[1] = loss;
        o[2] = loss;
        o[3] = expf(-red[0]);
    }
}

/* ------------------------------------------------------------------ */
extern "C" void kernel_launch(void* const* d_in, const int* in_sizes, int n_in,
                              void* d_out, int out_size) {
    const float* z    = (const float*)d_in[0];
    const int*   mask = (const int*)d_in[1];
    const float* e    = (const float*)d_in[2];
    float*       out  = (float*)d_out;

    cudaFuncSetAttribute(cand_kernel,
                         cudaFuncAttributeMaxDynamicSharedMemorySize, SM_TOT);
    cudaFuncSetAttribute(exact_kernel,
                         cudaFuncAttributeMaxDynamicSharedMemorySize, EX_TOT);

    eperm_kernel<<<NCODES * 128 / 256, 256>>>(e);   /* + fused zero-init */
    enorm_kernel<<<NCODES / 8, 256>>>(e);
    cand_kernel<<<NTOK / TQ, 256, SM_TOT>>>(z);
    exact_kernel<<<dim3(EX_SPL, NSEC), 256, EX_TOT>>>(z, e);
    gather_kernel<<<NTOK / 8, 256>>>(z, mask, e, out, out + 2 * (size_t)NC_OUT);
    finalize_kernel<<<1, 256>>>(out);
}

// round 17
// speedup vs baseline: 7.2073x; 1.1137x over previous
#include <cuda_runtime.h>
#include <cuda_bf16.h>
#include <cstdint>
#include <math.h>

#define NCODES 4096
#define CDIM   256
#define NTOK   32768
#define NC_OUT (NTOK * CDIM)

#define TQ      128              /* tokens per CTA           */
#define TNC     128              /* codes per tile           */
#define NTILES  (NCODES / TNC)   /* 32                       */
#define NSEC    (NTILES * 2)     /* 64 sectors of 64 codes   */
#define MARGIN  4e-4f

#define TILE_U32 16384           /* 64 KB per permuted tile  */

/* cand smem layout (bytes): A 64K | B0 64K | B1 64K | Es | secMin */
#define SM_A      0
#define SM_B0     65536
#define SM_B1     131072
#define SM_ES     196608
#define SM_SMIN   197120         /* 64 x 128 u32 = 32 KB (sector-major) */
#define SM_TOT    229888         /* < 227 KiB cap */

/* exact-kernel smem: e sector (64 x 257 f32) | enorm | 2 z bufs/warp */
#define EX_ESTRIDE 257
#define EX_E      0
#define EX_EN     65792
#define EX_Z      66048          /* 8 warps x 2 x 260 floats */
#define EX_TOT    82688          /* 2 CTAs/SM: 165376 B */
#define EX_SPL    8              /* grid 8 x 64 = 512 CTAs */

__device__ float          g_enorm[NCODES];
__device__ int            g_counts[NCODES];
__device__ float          g_loss;
__device__ int            g_valid;
__device__ unsigned long long g_key[NTOK];
__device__ int            g_lcnt[NSEC];
__device__ unsigned short g_list[NSEC * NTOK];               /* 4 MB  */
__device__ uint32_t       g_eperm[NTILES * TILE_U32];        /* 2 MB  */

/* order-preserving float<->uint key */
__device__ __forceinline__ unsigned fkey(float f) {
    unsigned u = __float_as_uint(f);
    return (u & 0x80000000u) ? ~u : (u | 0x80000000u);
}
__device__ __forceinline__ float funkey(unsigned k) {
    return (k & 0x80000000u) ? __uint_as_float(k & 0x7fffffffu)
                             : __uint_as_float(~k);
}
__device__ __forceinline__ uint32_t smem_u32(const void* p) {
    uint32_t a;
    asm("{ .reg .u64 t; cvta.to.shared.u64 t, %1; cvt.u32.u64 %0, t; }" : "=r"(a) : "l"(p));
    return a;
}
#define CP_ASYNC16(dst, src) \
    asm volatile("cp.async.cg.shared.global [%0], [%1], 16;" :: "r"(dst), "l"(src) : "memory")
#define CP_COMMIT()  asm volatile("cp.async.commit_group;" ::: "memory")
#define CP_WAIT(n)   asm volatile("cp.async.wait_group %0;" :: "n"(n) : "memory")

#define MMA_BF16(c, av, bv)                                                     \
    asm volatile("mma.sync.aligned.m16n8k16.row.col.f32.bf16.bf16.f32 "         \
        "{%0,%1,%2,%3}, {%4,%5,%6,%7}, {%8,%9}, {%0,%1,%2,%3};"                 \
        : "+f"((c)[0]), "+f"((c)[1]), "+f"((c)[2]), "+f"((c)[3])                \
        : "r"((av).x), "r"((av).y), "r"((av).z), "r"((av).w),                   \
          "r"((bv).x), "r"((bv).y))

/* ------------------------------------------------------------------ */
__global__ void enorm_kernel(const float* __restrict__ e) {
    int warp = (blockIdx.x * blockDim.x + threadIdx.x) >> 5;
    int lane = threadIdx.x & 31;
    if (warp >= NCODES) return;
    const float* row = e + (size_t)warp * CDIM;
    float s = 0.0f;
#pragma unroll
    for (int i = 0; i < CDIM / 32; i++) { float v = row[lane + 32 * i]; s += v * v; }
#pragma unroll
    for (int o = 16; o; o >>= 1) s += __shfl_down_sync(0xffffffffu, s, o);
    if (lane == 0) g_enorm[warp] = s;
}

/* ------------------------------------------------------------------ */
/* Pre-permute codebook to bf16 fragment layout + all zero-init work.  */
__global__ void eperm_kernel(const float* __restrict__ e) {
    int v = blockIdx.x * 256 + threadIdx.x;         /* NCODES*128 pairs */
    if (v < NCODES) g_counts[v] = 0;
    if (v < NTOK)   g_key[v] = 0xFFFFFFFFFFFFFFFFull;
    if (v < NSEC)   g_lcnt[v] = 0;
    if (v == 0) { g_loss = 0.0f; g_valid = 0; }

    int ng = v >> 7, kp = v & 127;
    float2 ev = *(const float2*)(e + (size_t)ng * CDIM + 2 * kp);
    __nv_bfloat162 h = __floats2bfloat162_rn(ev.x, ev.y);
    int tile = ng >> 7, n = ng & 127;
    int s = kp >> 3, kk = (2 * kp) & 15;
    int nt = n >> 3, nc = n & 7;
    int lanep = nc * 4 + ((kk >> 1) & 3);
    int reg   = kk >> 3;
    g_eperm[tile * TILE_U32 + (nt * 16 + s) * 64 + ((lanep * 2) ^ ((s & 3) << 1)) + reg]
        = *(unsigned*)&h;
}

/* ------------------------------------------------------------------ */
/* Single-pass bf16 mma.sync over 32 tiles; per-(token, 64-code        */
/* sector) minima of et = e_norm - 2*dot_bf16. Sectors with            */
/* secMin <= rowMin + MARGIN go to per-sector token lists. Margin      */
/* proof (rounds 8-14): any code achieving the exact reference argmin  */
/* has et <= et_min + MARGIN, so its sector is flagged.                */
__global__ void __launch_bounds__(256, 1)
cand_kernel(const float* __restrict__ z) {
    extern __shared__ char smem[];
    uint32_t* Asm    = (uint32_t*)(smem + SM_A);
    float*    Es     = (float*)(smem + SM_ES);
    unsigned* secMin = (unsigned*)(smem + SM_SMIN);   /* [64][128] sector-major */
    const uint32_t sbase = smem_u32(smem);

    const int tid    = threadIdx.x;
    const int lane   = tid & 31;
    const int wid    = tid >> 5;
    const int warp_m = wid >> 1;
    const int warp_n = wid & 1;
    const int g      = lane >> 2;
    const int tq     = lane & 3;

    for (int i = tid; i < TQ * NSEC; i += 256) secMin[i] = 0xFFFFFFFFu;

    /* B tile 0 via cp.async first (overlaps A conversion below) */
    {
        const uint32_t* Bg = g_eperm;
#pragma unroll
        for (int i = 0; i < 16; i++) {
            int o = (i * 256 + tid) * 4;
            CP_ASYNC16(sbase + SM_B0 + o * 4, Bg + o);
        }
        CP_COMMIT();
    }

    /* A: inline f32 -> bf16 fragment-permuted smem (once per CTA) */
    {
        const float2* zg = (const float2*)(z + (size_t)blockIdx.x * TQ * CDIM);
#pragma unroll 8
        for (int it = 0; it < 64; it++) {
            int v = it * 256 + tid;
            int m = v >> 7, kp = v & 127;
            float2 zv = zg[(size_t)m * 128 + kp];
            __nv_bfloat162 h = __floats2bfloat162_rn(zv.x, zv.y);
            int s  = kp >> 3;
            int kk = (2 * kp) & 15;
            int mt = m >> 4, lr = m & 15;
            int lanep = (lr & 7) * 4 + ((kk >> 1) & 3);
            int reg   = (lr >> 3) + 2 * (kk >> 3);
            Asm[(mt * 16 + s) * 128 + ((lanep * 4) ^ ((s & 3) << 2)) + reg]
                = *(unsigned*)&h;
        }
    }

    int buf = 0;
#pragma unroll 1
    for (int tile = 0; tile < NTILES; tile++) {
        const int jt = tile * TNC;
        if (tile + 1 < NTILES) {
            const uint32_t* Bg = g_eperm + (size_t)(tile + 1) * TILE_U32;
            uint32_t dstb = sbase + (buf ? SM_B0 : SM_B1);
#pragma unroll
            for (int i = 0; i < 16; i++) {
                int o = (i * 256 + tid) * 4;
                CP_ASYNC16(dstb + o * 4, Bg + o);
            }
            CP_COMMIT();
            CP_WAIT(1);
        } else {
            CP_WAIT(0);
        }
        if (tid < TNC) Es[tid] = g_enorm[jt + tid];
        __syncthreads();          /* also publishes Asm stores (tile 0) */

        const uint32_t* Bsm = (const uint32_t*)(smem + (buf ? SM_B1 : SM_B0));

        float acc[2][8][4];
#pragma unroll
        for (int mi = 0; mi < 2; mi++)
#pragma unroll
            for (int nj = 0; nj < 8; nj++)
#pragma unroll
                for (int r = 0; r < 4; r++) acc[mi][nj][r] = 0.0f;

#pragma unroll
        for (int s = 0; s < 16; s++) {
            uint4 a0 = *(const uint4*)(Asm + ((2 * warp_m + 0) * 16 + s) * 128 + ((lane * 4) ^ ((s & 3) << 2)));
            uint4 a1 = *(const uint4*)(Asm + ((2 * warp_m + 1) * 16 + s) * 128 + ((lane * 4) ^ ((s & 3) << 2)));
            uint2 bf[8];
#pragma unroll
            for (int nj = 0; nj < 8; nj++)
                bf[nj] = *(const uint2*)(Bsm + ((8 * warp_n + nj) * 16 + s) * 64 + ((lane * 2) ^ ((s & 3) << 1)));
#pragma unroll
            for (int nj = 0; nj < 8; nj++) {
                MMA_BF16(acc[0][nj], a0, bf[nj]);
                MMA_BF16(acc[1][nj], a1, bf[nj]);
            }
        }

        /* per-sector min: this warp's codes all lie in sector 2*tile+warp_n */
        float tmin[4] = {3.4e38f, 3.4e38f, 3.4e38f, 3.4e38f};
#pragma unroll
        for (int mi = 0; mi < 2; mi++)
#pragma unroll
            for (int nj = 0; nj < 8; nj++) {
                int colb = 64 * warp_n + 8 * nj + 2 * tq;
                float e0 = Es[colb], e1 = Es[colb + 1];
                tmin[2 * mi]     = fminf(tmin[2 * mi],     fmaf(-2.0f, acc[mi][nj][0], e0));
                tmin[2 * mi]     = fminf(tmin[2 * mi],     fmaf(-2.0f, acc[mi][nj][1], e1));
                tmin[2 * mi + 1] = fminf(tmin[2 * mi + 1], fmaf(-2.0f, acc[mi][nj][2], e0));
                tmin[2 * mi + 1] = fminf(tmin[2 * mi + 1], fmaf(-2.0f, acc[mi][nj][3], e1));
            }
        const int sec = 2 * tile + warp_n;
#pragma unroll
        for (int sl = 0; sl < 4; sl++) {
            float m_ = tmin[sl];
            m_ = fminf(m_, __shfl_xor_sync(0xffffffffu, m_, 1));
            m_ = fminf(m_, __shfl_xor_sync(0xffffffffu, m_, 2));
            if (tq == 0) {
                int row = 32 * warp_m + 16 * (sl >> 1) + 8 * (sl & 1) + g;
                atomicMin(secMin + sec * TQ + row, fkey(m_));
            }
        }
        __syncthreads();
        buf ^= 1;
    }

    /* flag sectors per token (key-space compares); append to lists */
    if (tid < TQ) {
        int row = tid;
        int tok = blockIdx.x * TQ + row;
        unsigned mk = 0xFFFFFFFFu;
#pragma unroll
        for (int s = 0; s < NSEC; s++)
            mk = min(mk, secMin[s * TQ + row]);
        unsigned thr_key = fkey(funkey(mk) + MARGIN);
#pragma unroll 1
        for (int s = 0; s < NSEC; s++) {
            if (secMin[s * TQ + row] <= thr_key) {
                int pos = atomicAdd(&g_lcnt[s], 1);
                g_list[s * NTOK + pos] = (unsigned short)tok;
            }
        }
    }
}

/* ------------------------------------------------------------------ */
/* Exact kernel (dual-token): for each flagged (token, sector), the    */
/* reference-exact d = fl(fl(Z - 2*dot) + e_norm) over the sector's 64 */
/* codes with sequential-k fp32 chains (round-4-validated ordering).   */
/* TWO tokens per warp share the e-row smem loads (2/3 the smem        */
/* traffic); each token's chains are bit-identical to the single-token */
/* version. Winner via atomicMin on (fkey(d)<<32)|idx (= reference min */
/* + first-index tie rule). Odd tails duplicate the last token         */
/* (atomicMin idempotent).                                             */
__global__ void __launch_bounds__(256, 2)
exact_kernel(const float* __restrict__ z, const float* __restrict__ e) {
    extern __shared__ char smem[];
    float* Esm  = (float*)(smem + EX_E);     /* [64][257] */
    float* ENsm = (float*)(smem + EX_EN);    /* [64]      */
    const int sec  = blockIdx.y;             /* 0..63 */
    const int spl  = blockIdx.x;             /* 0..EX_SPL-1 */
    const int tid  = threadIdx.x;
    const int lane = tid & 31;
    const int wid  = tid >> 5;
    float* zbuf1 = (float*)(smem + EX_Z) + wid * 520;
    float* zbuf2 = zbuf1 + 260;
    const int cbase = sec * 64;              /* first global code of sector */

    /* stage sector codes fp32 into padded smem */
    {
        const float* eb = e + (size_t)cbase * CDIM;
        for (int i = tid; i < 64 * CDIM; i += 256) {
            int c = i >> 8, k = i & 255;
            Esm[c * EX_ESTRIDE + k] = eb[i];
        }
        if (tid < 64) ENsm[tid] = g_enorm[cbase + tid];
    }
    __syncthreads();

    const int L     = g_lcnt[sec];
    const int nslot = EX_SPL * 8;            /* 64 warp-slots */
    const int slot  = spl * 8 + wid;

    for (int i = slot * 2; i < L; i += nslot * 2) {
        int tokA = g_list[sec * NTOK + i];
        int tokB = (i + 1 < L) ? g_list[sec * NTOK + i + 1] : tokA;
        {
            const float4* za = (const float4*)(z + (size_t)tokA * CDIM);
            const float4* zb = (const float4*)(z + (size_t)tokB * CDIM);
            ((float4*)zbuf1)[lane]      = za[lane];
            ((float4*)zbuf1)[lane + 32] = za[lane + 32];
            ((float4*)zbuf2)[lane]      = zb[lane];
            ((float4*)zbuf2)[lane + 32] = zb[lane + 32];
        }
        __syncwarp();

        /* 6 interleaved sequential fp32 chains (3 per token); e-row   */
        /* loads shared between the two tokens. Per-token arithmetic   */
        /* is bit-identical to the single-token version.               */
        float ZA = 0.0f, a0 = 0.0f, a1 = 0.0f;
        float ZB = 0.0f, b0 = 0.0f, b1 = 0.0f;
        const float* e0p = Esm + (lane +  0) * EX_ESTRIDE;
        const float* e1p = Esm + (lane + 32) * EX_ESTRIDE;
#pragma unroll 8
        for (int k = 0; k < CDIM; k++) {
            float ev0 = e0p[k];
            float ev1 = e1p[k];
            float za = zbuf1[k];
            float zb = zbuf2[k];
            ZA = __fmaf_rn(za, za, ZA);
            a0 = __fmaf_rn(za, ev0, a0);
            a1 = __fmaf_rn(za, ev1, a1);
            ZB = __fmaf_rn(zb, zb, ZB);
            b0 = __fmaf_rn(zb, ev0, b0);
            b1 = __fmaf_rn(zb, ev1, b1);
        }
        float en0 = ENsm[lane], en1 = ENsm[lane + 32];
        float vA0 = __fadd_rn(__fmaf_rn(-2.0f, a0, ZA), en0);
        float vA1 = __fadd_rn(__fmaf_rn(-2.0f, a1, ZA), en1);
        float vB0 = __fadd_rn(__fmaf_rn(-2.0f, b0, ZB), en0);
        float vB1 = __fadd_rn(__fmaf_rn(-2.0f, b1, ZB), en1);

        unsigned long long keyA =        ((unsigned long long)fkey(vA0) << 32) | (unsigned)(cbase + lane);
        keyA = min(keyA, ((unsigned long long)fkey(vA1) << 32) | (unsigned)(cbase + lane + 32));
        unsigned long long keyB =        ((unsigned long long)fkey(vB0) << 32) | (unsigned)(cbase + lane);
        keyB = min(keyB, ((unsigned long long)fkey(vB1) << 32) | (unsigned)(cbase + lane + 32));
#pragma unroll
        for (int o = 16; o; o >>= 1) {
            keyA = min(keyA, (unsigned long long)__shfl_xor_sync(0xffffffffu, keyA, o));
            keyB = min(keyB, (unsigned long long)__shfl_xor_sync(0xffffffffu, keyB, o));
        }
        if (lane == 0) {
            atomicMin(&g_key[tokA], keyA);
            atomicMin(&g_key[tokB], keyB);
        }
        __syncwarp();
    }
}

/* ------------------------------------------------------------------ */
/* Gather z_q/z_q_st + losses + histogram; resolves idx from key.      */
__global__ void gather_kernel(const float* __restrict__ z,
                              const int* __restrict__ mask,
                              const float* __restrict__ e,
                              float* __restrict__ out,
                              float* __restrict__ out_idx_f) {
    __shared__ float s_loss[8];
    __shared__ int   s_valid[8];
    int wid  = threadIdx.x >> 5;
    int lane = threadIdx.x & 31;
    int t    = blockIdx.x * 8 + wid;

    int mk  = mask[t];
    int idx = (int)(unsigned)(g_key[t] & 0xFFFFFFFFull);
    const float4* zr = (const float4*)(z + (size_t)t * CDIM);
    const float4* er = (const float4*)(e + (size_t)idx * CDIM);
    float4* o1 = (float4*)(out + (size_t)t * CDIM);
    float4* o2 = (float4*)(out + (size_t)NC_OUT + (size_t)t * CDIM);

    float ls = 0.0f;
#pragma unroll
    for (int i = 0; i < 2; i++) {
        int c = lane + 32 * i;
        float4 ev = er[c];
        float4 zv = zr[c];
        float4 q;
        if (mk) {
            q = ev;
            float dx = ev.x - zv.x, dy = ev.y - zv.y;
            float dz = ev.z - zv.z, dw = ev.w - zv.w;
            ls += dx * dx + dy * dy + dz * dz + dw * dw;
        } else {
            q = make_float4(0.0f, 0.0f, 0.0f, 0.0f);
        }
        o1[c] = q;
        o2[c] = q;
    }
#pragma unroll
    for (int o = 16; o; o >>= 1) ls += __shfl_down_sync(0xffffffffu, ls, o);
    if (lane == 0) {
        out_idx_f[t] = (float)idx;
        s_loss[wid]  = ls;
        s_valid[wid] = mk;
        if (mk) atomicAdd(&g_counts[idx], 1);
    }
    __syncthreads();
    if (threadIdx.x == 0) {
        float tot = 0.0f; int v = 0;
#pragma unroll
        for (int w = 0; w < 8; w++) { tot += s_loss[w]; v += s_valid[w]; }
        atomicAdd(&g_loss, tot);
        atomicAdd(&g_valid, v);
    }
}

/* ------------------------------------------------------------------ */
__global__ void finalize_kernel(float* __restrict__ out) {
    __shared__ float red[256];
    int tid = threadIdx.x;
    float nv    = (float)g_valid;
    float denom = nv + 1e-8f;
    float ent = 0.0f;
    for (int i = tid; i < NCODES; i += 256) {
        float p = (float)g_counts[i] / denom;
        ent += p * logf(p + 1e-8f);
    }
    red[tid] = ent;
    __syncthreads();
    for (int s = 128; s; s >>= 1) {
        if (tid < s) red[tid] += red[tid + s];
        __syncthreads();
    }
    if (tid == 0) {
        float valid = fmaxf(nv, 1.0f);
        float loss  = g_loss / valid;
        float* o = out + 2 * (size_t)NC_OUT + NTOK;
        o[0] = loss * 1.25f;
        o[1] = loss;
        o[2] = loss;
        o[3] = expf(-red[0]);
    }
}

/* ------------------------------------------------------------------ */
extern "C" void kernel_launch(void* const* d_in, const int* in_sizes, int n_in,
                              void* d_out, int out_size) {
    const float* z    = (const float*)d_in[0];
    const int*   mask = (const int*)d_in[1];
    const float* e    = (const float*)d_in[2];
    float*       out  = (float*)d_out;

    cudaFuncSetAttribute(cand_kernel,
                         cudaFuncAttributeMaxDynamicSharedMemorySize, SM_TOT);
    cudaFuncSetAttribute(exact_kernel,
                         cudaFuncAttributeMaxDynamicSharedMemorySize, EX_TOT);

    eperm_kernel<<<NCODES * 128 / 256, 256>>>(e);   /* + fused zero-init */
    enorm_kernel<<<NCODES / 8, 256>>>(e);
    cand_kernel<<<NTOK / TQ, 256, SM_TOT>>>(z);
    exact_kernel<<<dim3(EX_SPL, NSEC), 256, EX_TOT>>>(z, e);
    gather_kernel<<<NTOK / 8, 256>>>(z, mask, e, out, out + 2 * (size_t)NC_OUT);
    finalize_kernel<<<1, 256>>>(out);
}